// round 9
// baseline (speedup 1.0000x reference)
#include <cuda_runtime.h>
#include <math.h>
#include <stdint.h>

// Problem constants (fixed by the reference)
#define T_LEN 128
#define B_ENV 4096
#define N_TOT (T_LEN * B_ENV)   // 524288
#define HID   128
#define NA    6

// ---------------------------------------------------------------------------
// Scratch (device globals — no runtime allocation allowed)
// ---------------------------------------------------------------------------
__device__ float g_f2[(size_t)N_TOT * 256];   // 512 MB  (f2 activations)
__device__ float g_gx[(size_t)N_TOT * 512];   // 1 GB    (precomputed x-gates)
__device__ float g_wg[36 * 512];              // combined gx weight, k-major
__device__ float g_bg[512];                   // combined gate bias

__device__ __forceinline__ float sigf(float x) { return 1.f / (1.f + expf(-x)); }

// ---------------------------------------------------------------------------
// Packed f32x2 helpers
// ---------------------------------------------------------------------------
typedef unsigned long long u64;
__device__ __forceinline__ u64 pack2(float lo, float hi) {
    u64 r; asm("mov.b64 %0, {%1, %2};" : "=l"(r) : "f"(lo), "f"(hi)); return r;
}
__device__ __forceinline__ u64 dup2(float x) {
    u64 r; asm("mov.b64 %0, {%1, %1};" : "=l"(r) : "f"(x)); return r;
}
__device__ __forceinline__ void fma2(u64& acc, u64 a, u64 b) {
    asm("fma.rn.f32x2 %0, %1, %2, %0;" : "+l"(acc) : "l"(a), "l"(b));
}
__device__ __forceinline__ u64 fma2o(u64 a, u64 b, u64 c) {
    u64 r; asm("fma.rn.f32x2 %0, %1, %2, %3;" : "=l"(r) : "l"(a), "l"(b), "l"(c));
    return r;
}
__device__ __forceinline__ void unpack2(u64 v, float& lo, float& hi) {
    asm("mov.b64 {%0, %1}, %2;" : "=f"(lo), "=f"(hi) : "l"(v));
}

// ---------------------------------------------------------------------------
// Weight prep: combined gx weight (k-major [36][512]) and bias.
// ---------------------------------------------------------------------------
__global__ void prep_wg(const float* __restrict__ Wih, const float* __restrict__ Wl,
                        const float* __restrict__ We, float* __restrict__ out)
{
    int idx = blockIdx.x * 256 + threadIdx.x;
    if (idx >= 36 * 512) return;
    int k = idx >> 9, n = idx & 511;
    float v = 0.f;
    if (k < 32) {
        v = Wih[n * 96 + k];
    } else if (k < 34) {
        int d = k - 32;
        float s = 0.f;
        for (int j = 0; j < 32; j++) s += Wl[d * 32 + j] * Wih[n * 96 + 32 + j];
        v = s * 0.1f;
    } else if (k == 34) {
        float s = 0.f;
        for (int j = 0; j < 32; j++) s += We[j] * Wih[n * 96 + 64 + j];
        v = s * (1.f / 200.f);
    }
    out[k * 512 + n] = v;
}

__global__ void prep_bg(const float* __restrict__ Wih, const float* __restrict__ bl,
                        const float* __restrict__ be, const float* __restrict__ bih,
                        const float* __restrict__ bhh, float* __restrict__ bg)
{
    int n = blockIdx.x * 256 + threadIdx.x;
    if (n >= 512) return;
    float s = bih[n] + bhh[n];
    for (int j = 0; j < 32; j++)
        s += bl[j] * Wih[n * 96 + 32 + j] + be[j] * Wih[n * 96 + 64 + j];
    bg[n] = s;
}

// ---------------------------------------------------------------------------
// Fused L1+L2: image -> f1 (SMEM, k-major) -> f2 (global, relu)
// 512 threads, tile 128 x 256; per-thread 16 rows (8 pairs) x 4 cols.
// A via broadcast LDS.128, B one LDS.128 per thread per k.
// ---------------------------------------------------------------------------
#define S1 132   // k-major row stride in floats (132*4 % 16 == 0)

__global__ __launch_bounds__(512) void fused12(
    const float* __restrict__ img, const float* __restrict__ W1,
    const float* __restrict__ b1, const float* __restrict__ W2,
    const float* __restrict__ b2, float* __restrict__ f2)
{
    extern __shared__ float sm[];
    float* f1k = sm;                     // [256][S1]
    float* xsk = f1k + 256 * S1;         // [26][S1]
    float* bs  = xsk + 26 * S1;          // [32][264] double-buffered B

    const int tid = threadIdx.x;
    const int rg = tid >> 6;             // 0..7  rows rg*16 .. +15
    const int cg = tid & 63;             // 0..63 cols cg*4 .. +3
    const int rowBase = blockIdx.x * 128;

    // stage image (k-major, scaled) and W1
    for (int i = tid; i < 128 * 25; i += 512) {
        int k = i % 25, m = i / 25;
        xsk[k * S1 + m] = img[(size_t)(rowBase + m) * 25 + k] * (1.f / 255.f);
    }
    for (int i = tid; i < 25 * 256; i += 512) {
        int k = i >> 8, n = i & 255;
        bs[k * 264 + n] = W1[i];
    }
    __syncthreads();

    u64 acc[8][4];
#pragma unroll
    for (int p = 0; p < 8; p++)
#pragma unroll
        for (int j = 0; j < 4; j++) acc[p][j] = 0ull;

    // ---------------- phase 1: f1 = relu(x @ W1 + b1), K=25 ----------------
    for (int k = 0; k < 25; k++) {
        const ulonglong2* ap = (const ulonglong2*)(xsk + k * S1 + rg * 16);
        ulonglong2 A0 = ap[0], A1 = ap[1], A2 = ap[2], A3 = ap[3];
        u64 av[8] = {A0.x, A0.y, A1.x, A1.y, A2.x, A2.y, A3.x, A3.y};
        float4 q = *(const float4*)(bs + k * 264 + cg * 4);
        float bv[4] = {q.x, q.y, q.z, q.w};
#pragma unroll
        for (int j = 0; j < 4; j++) {
            u64 bd = dup2(bv[j]);
#pragma unroll
            for (int p = 0; p < 8; p++) fma2(acc[p][j], av[p], bd);
        }
    }
    {   // epilogue 1: bias+relu -> f1k (k-major)
        float4 c1 = *(const float4*)(b1 + cg * 4);
        float bias1[4] = {c1.x, c1.y, c1.z, c1.w};
#pragma unroll
        for (int p = 0; p < 8; p++) {
            int m0 = rg * 16 + 2 * p;
#pragma unroll
            for (int j = 0; j < 4; j++) {
                float o0, o1;
                unpack2(acc[p][j], o0, o1);
                o0 = fmaxf(o0 + bias1[j], 0.f);
                o1 = fmaxf(o1 + bias1[j], 0.f);
                *(u64*)&f1k[(cg * 4 + j) * S1 + m0] = pack2(o0, o1);
            }
        }
    }

    // ---------------- phase 2: f2 = relu(f1 @ W2 + b2), K=256 ---------------
    float ldr[8];
#define LOADW2(c)                                                      \
    _Pragma("unroll") for (int i = 0; i < 8; i++) {                    \
        int idx = tid + i * 512;                                       \
        int k = idx >> 8, n = idx & 255;                               \
        ldr[i] = W2[(size_t)((c) * 16 + k) * 256 + n];                 \
    }
#define STW2(buf)                                                      \
    _Pragma("unroll") for (int i = 0; i < 8; i++) {                    \
        int idx = tid + i * 512;                                       \
        int k = idx >> 8, n = idx & 255;                               \
        bs[((buf) * 16 + k) * 264 + n] = ldr[i];                       \
    }

    LOADW2(0);
    __syncthreads();           // f1k complete; bs (W1) no longer needed
    STW2(0);
    __syncthreads();

#pragma unroll
    for (int p = 0; p < 8; p++)
#pragma unroll
        for (int j = 0; j < 4; j++) acc[p][j] = 0ull;

    for (int c = 0; c < 16; c++) {
        if (c < 15) { LOADW2(c + 1); }
        const float* bsc = bs + (c & 1) * 16 * 264;
        const float* f1c = f1k + c * 16 * S1;
#pragma unroll
        for (int k = 0; k < 16; k++) {
            const ulonglong2* ap = (const ulonglong2*)(f1c + k * S1 + rg * 16);
            ulonglong2 A0 = ap[0], A1 = ap[1], A2 = ap[2], A3 = ap[3];
            u64 av[8] = {A0.x, A0.y, A1.x, A1.y, A2.x, A2.y, A3.x, A3.y};
            float4 q = *(const float4*)(bsc + k * 264 + cg * 4);
            float bv[4] = {q.x, q.y, q.z, q.w};
#pragma unroll
            for (int j = 0; j < 4; j++) {
                u64 bd = dup2(bv[j]);
#pragma unroll
                for (int p = 0; p < 8; p++) fma2(acc[p][j], av[p], bd);
            }
        }
        if (c < 15) { STW2((c + 1) & 1); }
        __syncthreads();
    }
#undef LOADW2
#undef STW2

    {   // epilogue 2 -> global f2
        float4 c2 = *(const float4*)(b2 + cg * 4);
        float bias2[4] = {c2.x, c2.y, c2.z, c2.w};
#pragma unroll
        for (int p = 0; p < 8; p++) {
            int m0 = rowBase + rg * 16 + 2 * p;
            float o0[4], o1[4];
#pragma unroll
            for (int j = 0; j < 4; j++) {
                unpack2(acc[p][j], o0[j], o1[j]);
                o0[j] = fmaxf(o0[j] + bias2[j], 0.f);
                o1[j] = fmaxf(o1[j] + bias2[j], 0.f);
            }
            *(float4*)&f2[(size_t)m0 * 256 + cg * 4] =
                make_float4(o0[0], o0[1], o0[2], o0[3]);
            *(float4*)&f2[(size_t)(m0 + 1) * 256 + cg * 4] =
                make_float4(o1[0], o1[1], o1[2], o1[3]);
        }
    }
}

// ---------------------------------------------------------------------------
// Fused L3+L4+loc/eng+gx
// ---------------------------------------------------------------------------
#define S3 132

__global__ __launch_bounds__(512) void fused345(
    const float* __restrict__ f2, const float* __restrict__ loc,
    const float* __restrict__ eng,
    const float* __restrict__ W3, const float* __restrict__ b3,
    const float* __restrict__ W4, const float* __restrict__ b4,
    const float* __restrict__ wg, const float* __restrict__ bg,
    float* __restrict__ gx)
{
    extern __shared__ float sm[];
    float* f3k = sm;                      // [128][S3]
    float* f4k = f3k + 128 * S3;          // [36][S3]
    float* as2 = f4k + 36 * S3;           // 2 x [16][S3]
    float* bs3 = as2 + 32 * S3;           // 2 x [16][132]
    float* bsg = bs3 + 32 * 132;          // [36][516]

    const int tid = threadIdx.x;
    const int rowBase = blockIdx.x * 128;

    // stage full Wg
    for (int i = tid; i < 36 * 512; i += 512) {
        int k = i >> 9, n = i & 511;
        bsg[k * 516 + n] = wg[i];
    }

    // ============ phase L3: f3 = relu(f2 @ W3 + b3), K=256 ============
    {
        const int rg = tid >> 5;          // 0..15 rows rg*8..+7
        const int cg = tid & 31;          // cols cg*4..+3
        u64 acc[4][4];
#pragma unroll
        for (int p = 0; p < 4; p++)
#pragma unroll
            for (int j = 0; j < 4; j++) acc[p][j] = 0ull;

        float lA[4], lB[4];
#define LD3(c)                                                         \
    _Pragma("unroll") for (int i = 0; i < 4; i++) {                    \
        int idx = tid + i * 512;                                       \
        int ka = idx & 15, ma = idx >> 4;                              \
        lA[i] = f2[(size_t)(rowBase + ma) * 256 + (c) * 16 + ka];      \
        int nb = idx & 127, kb = idx >> 7;                             \
        lB[i] = W3[(size_t)((c) * 16 + kb) * 128 + nb];                \
    }
#define ST3(buf)                                                       \
    _Pragma("unroll") for (int i = 0; i < 4; i++) {                    \
        int idx = tid + i * 512;                                       \
        int ka = idx & 15, ma = idx >> 4;                              \
        as2[((buf) * 16 + ka) * S3 + ma] = lA[i];                      \
        int nb = idx & 127, kb = idx >> 7;                             \
        bs3[((buf) * 16 + kb) * 132 + nb] = lB[i];                     \
    }
        LD3(0); ST3(0);
        __syncthreads();
        for (int c = 0; c < 16; c++) {
            if (c < 15) { LD3(c + 1); }
            const float* ab = as2 + (c & 1) * 16 * S3;
            const float* bb = bs3 + (c & 1) * 16 * 132;
#pragma unroll
            for (int k = 0; k < 16; k++) {
                const ulonglong2* ap = (const ulonglong2*)(ab + k * S3 + rg * 8);
                ulonglong2 A0 = ap[0], A1 = ap[1];
                u64 av[4] = {A0.x, A0.y, A1.x, A1.y};
                float4 q = *(const float4*)(bb + k * 132 + cg * 4);
                float bv[4] = {q.x, q.y, q.z, q.w};
#pragma unroll
                for (int j = 0; j < 4; j++) {
                    u64 bd = dup2(bv[j]);
#pragma unroll
                    for (int p = 0; p < 4; p++) fma2(acc[p][j], av[p], bd);
                }
            }
            if (c < 15) { ST3((c + 1) & 1); }
            __syncthreads();
        }
#undef LD3
#undef ST3
        float4 cb = *(const float4*)(b3 + cg * 4);
        float bias0[4] = {cb.x, cb.y, cb.z, cb.w};
#pragma unroll
        for (int p = 0; p < 4; p++) {
            int m0 = rg * 8 + 2 * p;
#pragma unroll
            for (int j = 0; j < 4; j++) {
                float o0, o1;
                unpack2(acc[p][j], o0, o1);
                o0 = fmaxf(o0 + bias0[j], 0.f);
                o1 = fmaxf(o1 + bias0[j], 0.f);
                *(u64*)&f3k[(cg * 4 + j) * S3 + m0] = pack2(o0, o1);
            }
        }
    }
    __syncthreads();

    // ============ phase L4: f4 = relu(f3 @ W4 + b4), K=128 ============
    {
        const int tr4 = tid >> 3;         // 0..63 rows tr4*2
        const int tc4 = tid & 7;          // cols tc4*4
        u64 acc[4] = {0ull, 0ull, 0ull, 0ull};
#pragma unroll 4
        for (int k = 0; k < 128; k++) {
            u64 a = *(const u64*)&f3k[k * S3 + tr4 * 2];
            float4 q = *(const float4*)&W4[k * 32 + tc4 * 4];
            float bv[4] = {q.x, q.y, q.z, q.w};
#pragma unroll
            for (int j = 0; j < 4; j++) fma2(acc[j], a, dup2(bv[j]));
        }
        float4 cb = *(const float4*)(b4 + tc4 * 4);
        float bias0[4] = {cb.x, cb.y, cb.z, cb.w};
#pragma unroll
        for (int j = 0; j < 4; j++) {
            float o0, o1;
            unpack2(acc[j], o0, o1);
            o0 = fmaxf(o0 + bias0[j], 0.f);
            o1 = fmaxf(o1 + bias0[j], 0.f);
            *(u64*)&f4k[(tc4 * 4 + j) * S3 + tr4 * 2] = pack2(o0, o1);
        }
        if (tid < 128) {
            int n = rowBase + tid;
            f4k[32 * S3 + tid] = loc[2 * n];
            f4k[33 * S3 + tid] = loc[2 * n + 1];
            f4k[34 * S3 + tid] = eng[n];
            f4k[35 * S3 + tid] = 0.f;
        }
    }
    __syncthreads();

    // ============ phase gx: gates = f4e @ Wg + bg, K=36 ============
    {
        const int rg = tid >> 6;          // 0..7  rows rg*16..+15
        const int cg = tid & 63;          // cols cg*4..+3 (per 256-col pass)
        for (int pc = 0; pc < 2; pc++) {
            u64 acc[8][4];
#pragma unroll
            for (int p = 0; p < 8; p++)
#pragma unroll
                for (int j = 0; j < 4; j++) acc[p][j] = 0ull;

#pragma unroll 4
            for (int k = 0; k < 36; k++) {
                const ulonglong2* ap = (const ulonglong2*)(f4k + k * S3 + rg * 16);
                ulonglong2 A0 = ap[0], A1 = ap[1], A2 = ap[2], A3 = ap[3];
                u64 av[8] = {A0.x, A0.y, A1.x, A1.y, A2.x, A2.y, A3.x, A3.y};
                float4 q = *(const float4*)(bsg + k * 516 + pc * 256 + cg * 4);
                float bv[4] = {q.x, q.y, q.z, q.w};
#pragma unroll
                for (int j = 0; j < 4; j++) {
                    u64 bd = dup2(bv[j]);
#pragma unroll
                    for (int p = 0; p < 8; p++) fma2(acc[p][j], av[p], bd);
                }
            }
            float4 cb = *(const float4*)(bg + pc * 256 + cg * 4);
            float bias0[4] = {cb.x, cb.y, cb.z, cb.w};
#pragma unroll
            for (int p = 0; p < 8; p++) {
                int m0 = rowBase + rg * 16 + 2 * p;
                float o0[4], o1[4];
#pragma unroll
                for (int j = 0; j < 4; j++) {
                    unpack2(acc[p][j], o0[j], o1[j]);
                    o0[j] += bias0[j];
                    o1[j] += bias0[j];
                }
                *(float4*)&gx[(size_t)m0 * 512 + pc * 256 + cg * 4] =
                    make_float4(o0[0], o0[1], o0[2], o0[3]);
                *(float4*)&gx[(size_t)(m0 + 1) * 512 + pc * 256 + cg * 4] =
                    make_float4(o1[0], o1[1], o1[2], o1[3]);
            }
        }
    }
}

// ---------------------------------------------------------------------------
// LSTM: one CTA owns 8 batch rows (512 CTAs), 2 barriers per timestep.
// done-mask folded algebraically: gates = gx + m[r]*(Whh @ h);
// c-mask applied in update. Heads(t-1) folded into gates(t) phase.
// ---------------------------------------------------------------------------
__global__ __launch_bounds__(512) void lstm_v3(
    const float* __restrict__ gx, const int* __restrict__ done,
    const float* __restrict__ h0, const float* __restrict__ c0,
    const float* __restrict__ Whh,
    const float* __restrict__ Wa, const float* __restrict__ ba,
    const float* __restrict__ Wc, const float* __restrict__ bc,
    float* __restrict__ out)
{
    __shared__ __align__(16) float h_s[HID][8];   // 4 KB (unmasked h)
    __shared__ float gs[4 * HID][9];              // 18 KB padded
    __shared__ float msall[T_LEN * 8];            // 4 KB per-step row masks

    const int tid = threadIdx.x;
    const int r0 = blockIdx.x * 8;

    float creg[2];
#pragma unroll
    for (int i = 0; i < 2; i++) {
        int e = tid + i * 512;
        int k = e >> 3, r = e & 7;
        h_s[k][r] = h0[(r0 + r) * HID + k];
        creg[i] = c0[(r0 + r) * HID + k];
    }
#pragma unroll
    for (int i = 0; i < 2; i++) {
        int e = tid + i * 512;
        int t = e >> 3, r = e & 7;
        msall[e] = done[t * B_ENV + r0 + r] ? 0.f : 1.f;
    }
    __syncthreads();

    for (int t = 0; t < T_LEN; t++) {
        // ---- heads for step t-1 (56 threads) + gates(t) (all threads) ----
        if (t > 0 && tid < 8 * (NA + 1)) {
            int r = tid / (NA + 1), col = tid % (NA + 1);
            float s = (col < NA) ? ba[col] : bc[0];
            if (col < NA) {
#pragma unroll 8
                for (int k = 0; k < HID; k++) s += h_s[k][r] * Wa[k * NA + col];
            } else {
#pragma unroll 8
                for (int k = 0; k < HID; k++) s += h_s[k][r] * Wc[k];
            }
            out[((size_t)(t - 1) * B_ENV + r0 + r) * (NA + 1) + col] = s;
        }
        {
            const float* gp = gx + ((size_t)t * B_ENV + r0) * 512 + tid;
            u64 gxp[4];
#pragma unroll
            for (int p = 0; p < 4; p++)
                gxp[p] = pack2(gp[(size_t)(2 * p) * 512], gp[(size_t)(2 * p + 1) * 512]);

            u64 macc[4] = {0ull, 0ull, 0ull, 0ull};
            const float4* w4 = (const float4*)(Whh + (size_t)tid * HID);
#pragma unroll 8
            for (int kk = 0; kk < 32; kk++) {
                float4 w = w4[kk];
                float wv[4] = {w.x, w.y, w.z, w.w};
#pragma unroll
                for (int s = 0; s < 4; s++) {
                    int k = kk * 4 + s;
                    u64 wd = dup2(wv[s]);
                    const ulonglong2* hp = (const ulonglong2*)&h_s[k][0];
                    ulonglong2 hA = hp[0], hB = hp[1];
                    fma2(macc[0], wd, hA.x); fma2(macc[1], wd, hA.y);
                    fma2(macc[2], wd, hB.x); fma2(macc[3], wd, hB.y);
                }
            }
            const float* ms = &msall[t * 8];
#pragma unroll
            for (int p = 0; p < 4; p++) {
                u64 mp = pack2(ms[2 * p], ms[2 * p + 1]);
                u64 res = fma2o(macc[p], mp, gxp[p]);
                float lo, hi;
                unpack2(res, lo, hi);
                gs[tid][2 * p] = lo;
                gs[tid][2 * p + 1] = hi;
            }
        }
        __syncthreads();

        // ---- update: c = sig(f)*(m*c) + sig(i)*tanh(g); h = sig(o)*tanh(c) ----
#pragma unroll
        for (int i = 0; i < 2; i++) {
            int e = tid + i * 512;
            int k = e >> 3, r = e & 7;
            float m = msall[t * 8 + r];
            float ig = gs[k][r];
            float fg = gs[HID + k][r];
            float gg = gs[2 * HID + k][r];
            float og = gs[3 * HID + k][r];
            float c = sigf(fg) * (creg[i] * m) + sigf(ig) * tanhf(gg);
            creg[i] = c;
            h_s[k][r] = sigf(og) * tanhf(c);
        }
        __syncthreads();
    }

    // final heads (t = T_LEN-1)
    if (tid < 8 * (NA + 1)) {
        int r = tid / (NA + 1), col = tid % (NA + 1);
        float s = (col < NA) ? ba[col] : bc[0];
        if (col < NA) {
#pragma unroll 8
            for (int k = 0; k < HID; k++) s += h_s[k][r] * Wa[k * NA + col];
        } else {
#pragma unroll 8
            for (int k = 0; k < HID; k++) s += h_s[k][r] * Wc[k];
        }
        out[((size_t)(T_LEN - 1) * B_ENV + r0 + r) * (NA + 1) + col] = s;
    }
}

// ---------------------------------------------------------------------------
// Launch
// ---------------------------------------------------------------------------
extern "C" void kernel_launch(void* const* d_in, const int* in_sizes, int n_in,
                              void* d_out, int out_size)
{
    const float* image = (const float*)d_in[0];
    const float* location = (const float*)d_in[1];
    const float* energy = (const float*)d_in[2];
    const int*   done  = (const int*)d_in[3];
    const float* h0 = (const float*)d_in[4];
    const float* c0 = (const float*)d_in[5];
    const float* W1 = (const float*)d_in[6];
    const float* b1 = (const float*)d_in[7];
    const float* W2 = (const float*)d_in[8];
    const float* b2 = (const float*)d_in[9];
    const float* W3 = (const float*)d_in[10];
    const float* b3 = (const float*)d_in[11];
    const float* W4 = (const float*)d_in[12];
    const float* b4 = (const float*)d_in[13];
    const float* Wl = (const float*)d_in[14];
    const float* bl = (const float*)d_in[15];
    const float* We = (const float*)d_in[16];
    const float* be = (const float*)d_in[17];
    const float* Wih = (const float*)d_in[18];
    const float* Whh = (const float*)d_in[19];
    const float* bih = (const float*)d_in[20];
    const float* bhh = (const float*)d_in[21];
    const float* Wa = (const float*)d_in[22];
    const float* ba = (const float*)d_in[23];
    const float* Wc = (const float*)d_in[24];
    const float* bc = (const float*)d_in[25];
    float* out = (float*)d_out;

    float *pf2, *pgx, *pwg, *pbg;
    cudaGetSymbolAddress((void**)&pf2, g_f2);
    cudaGetSymbolAddress((void**)&pgx, g_gx);
    cudaGetSymbolAddress((void**)&pwg, g_wg);
    cudaGetSymbolAddress((void**)&pbg, g_bg);

    prep_wg<<<(36 * 512 + 255) / 256, 256>>>(Wih, Wl, We, pwg);
    prep_bg<<<2, 256>>>(Wih, bl, be, bih, bhh, pbg);

    const int smem12 = (256 * S1 + 26 * S1 + 32 * 264) * 4;
    const int smem345 = (128 * S3 + 36 * S3 + 32 * S3 + 32 * 132 + 36 * 516) * 4;
    cudaFuncSetAttribute(fused12, cudaFuncAttributeMaxDynamicSharedMemorySize, smem12);
    cudaFuncSetAttribute(fused345, cudaFuncAttributeMaxDynamicSharedMemorySize, smem345);

    const int MB = N_TOT / 128;   // 4096 row tiles

    fused12<<<MB, 512, smem12>>>(image, W1, b1, W2, b2, pf2);
    fused345<<<MB, 512, smem345>>>(pf2, location, energy, W3, b3, W4, b4, pwg, pbg, pgx);
    lstm_v3<<<B_ENV / 8, 512>>>(pgx, done, h0, c0, Whh, Wa, ba, Wc, bc, out);
}

// round 10
// speedup vs baseline: 1.3170x; 1.3170x over previous
#include <cuda_runtime.h>
#include <math.h>
#include <stdint.h>

// Problem constants (fixed by the reference)
#define T_LEN 128
#define B_ENV 4096
#define N_TOT (T_LEN * B_ENV)   // 524288
#define HID   128
#define NA    6

// ---------------------------------------------------------------------------
// Scratch (device globals — no runtime allocation allowed)
// ---------------------------------------------------------------------------
__device__ float g_f2[(size_t)N_TOT * 256];   // 512 MB (f2 acts; later reused as hs)
__device__ float g_gx[(size_t)N_TOT * 512];   // 1 GB   precomputed x-gates
__device__ float g_wg[36 * 512];              // combined gx weight, k-major
__device__ float g_bg[512];                   // combined gate bias

__device__ __forceinline__ float sigf(float x) { return 1.f / (1.f + expf(-x)); }

// ---------------------------------------------------------------------------
// Packed f32x2 helpers
// ---------------------------------------------------------------------------
typedef unsigned long long u64;
__device__ __forceinline__ u64 pack2(float lo, float hi) {
    u64 r; asm("mov.b64 %0, {%1, %2};" : "=l"(r) : "f"(lo), "f"(hi)); return r;
}
__device__ __forceinline__ u64 dup2(float x) {
    u64 r; asm("mov.b64 %0, {%1, %1};" : "=l"(r) : "f"(x)); return r;
}
__device__ __forceinline__ void fma2(u64& acc, u64 a, u64 b) {
    asm("fma.rn.f32x2 %0, %1, %2, %0;" : "+l"(acc) : "l"(a), "l"(b));
}
__device__ __forceinline__ u64 fma2o(u64 a, u64 b, u64 c) {
    u64 r; asm("fma.rn.f32x2 %0, %1, %2, %3;" : "=l"(r) : "l"(a), "l"(b), "l"(c));
    return r;
}
__device__ __forceinline__ void unpack2(u64 v, float& lo, float& hi) {
    asm("mov.b64 {%0, %1}, %2;" : "=f"(lo), "=f"(hi) : "l"(v));
}

// ---------------------------------------------------------------------------
// Weight prep: combined gx weight (k-major [36][512]) and bias.
// ---------------------------------------------------------------------------
__global__ void prep_wg(const float* __restrict__ Wih, const float* __restrict__ Wl,
                        const float* __restrict__ We, float* __restrict__ out)
{
    int idx = blockIdx.x * 256 + threadIdx.x;
    if (idx >= 36 * 512) return;
    int k = idx >> 9, n = idx & 511;
    float v = 0.f;
    if (k < 32) {
        v = Wih[n * 96 + k];
    } else if (k < 34) {
        int d = k - 32;
        float s = 0.f;
        for (int j = 0; j < 32; j++) s += Wl[d * 32 + j] * Wih[n * 96 + 32 + j];
        v = s * 0.1f;
    } else if (k == 34) {
        float s = 0.f;
        for (int j = 0; j < 32; j++) s += We[j] * Wih[n * 96 + 64 + j];
        v = s * (1.f / 200.f);
    }
    out[k * 512 + n] = v;
}

__global__ void prep_bg(const float* __restrict__ Wih, const float* __restrict__ bl,
                        const float* __restrict__ be, const float* __restrict__ bih,
                        const float* __restrict__ bhh, float* __restrict__ bg)
{
    int n = blockIdx.x * 256 + threadIdx.x;
    if (n >= 512) return;
    float s = bih[n] + bhh[n];
    for (int j = 0; j < 32; j++)
        s += bl[j] * Wih[n * 96 + 32 + j] + be[j] * Wih[n * 96 + 64 + j];
    bg[n] = s;
}

// ---------------------------------------------------------------------------
// Fused L1+L2 (R9 tiling: per-thread 16 rows x 4 cols, aligned S1=132)
// ---------------------------------------------------------------------------
#define S1 132

__global__ __launch_bounds__(512) void fused12(
    const float* __restrict__ img, const float* __restrict__ W1,
    const float* __restrict__ b1, const float* __restrict__ W2,
    const float* __restrict__ b2, float* __restrict__ f2)
{
    extern __shared__ float sm[];
    float* f1k = sm;                     // [256][S1]
    float* xsk = f1k + 256 * S1;         // [26][S1]
    float* bs  = xsk + 26 * S1;          // [32][264] double-buffered B

    const int tid = threadIdx.x;
    const int rg = tid >> 6;             // 0..7  rows rg*16 .. +15
    const int cg = tid & 63;             // 0..63 cols cg*4 .. +3
    const int rowBase = blockIdx.x * 128;

    for (int i = tid; i < 128 * 25; i += 512) {
        int k = i % 25, m = i / 25;
        xsk[k * S1 + m] = img[(size_t)(rowBase + m) * 25 + k] * (1.f / 255.f);
    }
    for (int i = tid; i < 25 * 256; i += 512) {
        int k = i >> 8, n = i & 255;
        bs[k * 264 + n] = W1[i];
    }
    __syncthreads();

    u64 acc[8][4];
#pragma unroll
    for (int p = 0; p < 8; p++)
#pragma unroll
        for (int j = 0; j < 4; j++) acc[p][j] = 0ull;

    // phase 1: f1 = relu(x @ W1 + b1), K=25
    for (int k = 0; k < 25; k++) {
        const ulonglong2* ap = (const ulonglong2*)(xsk + k * S1 + rg * 16);
        ulonglong2 A0 = ap[0], A1 = ap[1], A2 = ap[2], A3 = ap[3];
        u64 av[8] = {A0.x, A0.y, A1.x, A1.y, A2.x, A2.y, A3.x, A3.y};
        float4 q = *(const float4*)(bs + k * 264 + cg * 4);
        float bv[4] = {q.x, q.y, q.z, q.w};
#pragma unroll
        for (int j = 0; j < 4; j++) {
            u64 bd = dup2(bv[j]);
#pragma unroll
            for (int p = 0; p < 8; p++) fma2(acc[p][j], av[p], bd);
        }
    }
    {
        float4 c1 = *(const float4*)(b1 + cg * 4);
        float bias1[4] = {c1.x, c1.y, c1.z, c1.w};
#pragma unroll
        for (int p = 0; p < 8; p++) {
            int m0 = rg * 16 + 2 * p;
#pragma unroll
            for (int j = 0; j < 4; j++) {
                float o0, o1;
                unpack2(acc[p][j], o0, o1);
                o0 = fmaxf(o0 + bias1[j], 0.f);
                o1 = fmaxf(o1 + bias1[j], 0.f);
                *(u64*)&f1k[(cg * 4 + j) * S1 + m0] = pack2(o0, o1);
            }
        }
    }

    // phase 2: f2 = relu(f1 @ W2 + b2), K=256
    float ldr[8];
#define LOADW2(c)                                                      \
    _Pragma("unroll") for (int i = 0; i < 8; i++) {                    \
        int idx = tid + i * 512;                                       \
        int k = idx >> 8, n = idx & 255;                               \
        ldr[i] = W2[(size_t)((c) * 16 + k) * 256 + n];                 \
    }
#define STW2(buf)                                                      \
    _Pragma("unroll") for (int i = 0; i < 8; i++) {                    \
        int idx = tid + i * 512;                                       \
        int k = idx >> 8, n = idx & 255;                               \
        bs[((buf) * 16 + k) * 264 + n] = ldr[i];                       \
    }

    LOADW2(0);
    __syncthreads();
    STW2(0);
    __syncthreads();

#pragma unroll
    for (int p = 0; p < 8; p++)
#pragma unroll
        for (int j = 0; j < 4; j++) acc[p][j] = 0ull;

    for (int c = 0; c < 16; c++) {
        if (c < 15) { LOADW2(c + 1); }
        const float* bsc = bs + (c & 1) * 16 * 264;
        const float* f1c = f1k + c * 16 * S1;
#pragma unroll
        for (int k = 0; k < 16; k++) {
            const ulonglong2* ap = (const ulonglong2*)(f1c + k * S1 + rg * 16);
            ulonglong2 A0 = ap[0], A1 = ap[1], A2 = ap[2], A3 = ap[3];
            u64 av[8] = {A0.x, A0.y, A1.x, A1.y, A2.x, A2.y, A3.x, A3.y};
            float4 q = *(const float4*)(bsc + k * 264 + cg * 4);
            float bv[4] = {q.x, q.y, q.z, q.w};
#pragma unroll
            for (int j = 0; j < 4; j++) {
                u64 bd = dup2(bv[j]);
#pragma unroll
                for (int p = 0; p < 8; p++) fma2(acc[p][j], av[p], bd);
            }
        }
        if (c < 15) { STW2((c + 1) & 1); }
        __syncthreads();
    }
#undef LOADW2
#undef STW2

    {
        float4 c2 = *(const float4*)(b2 + cg * 4);
        float bias2[4] = {c2.x, c2.y, c2.z, c2.w};
#pragma unroll
        for (int p = 0; p < 8; p++) {
            int m0 = rowBase + rg * 16 + 2 * p;
            float o0[4], o1[4];
#pragma unroll
            for (int j = 0; j < 4; j++) {
                unpack2(acc[p][j], o0[j], o1[j]);
                o0[j] = fmaxf(o0[j] + bias2[j], 0.f);
                o1[j] = fmaxf(o1[j] + bias2[j], 0.f);
            }
            *(float4*)&f2[(size_t)m0 * 256 + cg * 4] =
                make_float4(o0[0], o0[1], o0[2], o0[3]);
            *(float4*)&f2[(size_t)(m0 + 1) * 256 + cg * 4] =
                make_float4(o1[0], o1[1], o1[2], o1[3]);
        }
    }
}

// ---------------------------------------------------------------------------
// Fused L3+L4+loc/eng+gx (R9 version)
// ---------------------------------------------------------------------------
#define S3 132

__global__ __launch_bounds__(512) void fused345(
    const float* __restrict__ f2, const float* __restrict__ loc,
    const float* __restrict__ eng,
    const float* __restrict__ W3, const float* __restrict__ b3,
    const float* __restrict__ W4, const float* __restrict__ b4,
    const float* __restrict__ wg, const float* __restrict__ bg,
    float* __restrict__ gx)
{
    extern __shared__ float sm[];
    float* f3k = sm;                      // [128][S3]
    float* f4k = f3k + 128 * S3;          // [36][S3]
    float* as2 = f4k + 36 * S3;           // 2 x [16][S3]
    float* bs3 = as2 + 32 * S3;           // 2 x [16][132]
    float* bsg = bs3 + 32 * 132;          // [36][516]

    const int tid = threadIdx.x;
    const int rowBase = blockIdx.x * 128;

    for (int i = tid; i < 36 * 512; i += 512) {
        int k = i >> 9, n = i & 511;
        bsg[k * 516 + n] = wg[i];
    }

    // phase L3
    {
        const int rg = tid >> 5;
        const int cg = tid & 31;
        u64 acc[4][4];
#pragma unroll
        for (int p = 0; p < 4; p++)
#pragma unroll
            for (int j = 0; j < 4; j++) acc[p][j] = 0ull;

        float lA[4], lB[4];
#define LD3(c)                                                         \
    _Pragma("unroll") for (int i = 0; i < 4; i++) {                    \
        int idx = tid + i * 512;                                       \
        int ka = idx & 15, ma = idx >> 4;                              \
        lA[i] = f2[(size_t)(rowBase + ma) * 256 + (c) * 16 + ka];      \
        int nb = idx & 127, kb = idx >> 7;                             \
        lB[i] = W3[(size_t)((c) * 16 + kb) * 128 + nb];                \
    }
#define ST3(buf)                                                       \
    _Pragma("unroll") for (int i = 0; i < 4; i++) {                    \
        int idx = tid + i * 512;                                       \
        int ka = idx & 15, ma = idx >> 4;                              \
        as2[((buf) * 16 + ka) * S3 + ma] = lA[i];                      \
        int nb = idx & 127, kb = idx >> 7;                             \
        bs3[((buf) * 16 + kb) * 132 + nb] = lB[i];                     \
    }
        LD3(0); ST3(0);
        __syncthreads();
        for (int c = 0; c < 16; c++) {
            if (c < 15) { LD3(c + 1); }
            const float* ab = as2 + (c & 1) * 16 * S3;
            const float* bb = bs3 + (c & 1) * 16 * 132;
#pragma unroll
            for (int k = 0; k < 16; k++) {
                const ulonglong2* ap = (const ulonglong2*)(ab + k * S3 + rg * 8);
                ulonglong2 A0 = ap[0], A1 = ap[1];
                u64 av[4] = {A0.x, A0.y, A1.x, A1.y};
                float4 q = *(const float4*)(bb + k * 132 + cg * 4);
                float bv[4] = {q.x, q.y, q.z, q.w};
#pragma unroll
                for (int j = 0; j < 4; j++) {
                    u64 bd = dup2(bv[j]);
#pragma unroll
                    for (int p = 0; p < 4; p++) fma2(acc[p][j], av[p], bd);
                }
            }
            if (c < 15) { ST3((c + 1) & 1); }
            __syncthreads();
        }
#undef LD3
#undef ST3
        float4 cb = *(const float4*)(b3 + cg * 4);
        float bias0[4] = {cb.x, cb.y, cb.z, cb.w};
#pragma unroll
        for (int p = 0; p < 4; p++) {
            int m0 = rg * 8 + 2 * p;
#pragma unroll
            for (int j = 0; j < 4; j++) {
                float o0, o1;
                unpack2(acc[p][j], o0, o1);
                o0 = fmaxf(o0 + bias0[j], 0.f);
                o1 = fmaxf(o1 + bias0[j], 0.f);
                *(u64*)&f3k[(cg * 4 + j) * S3 + m0] = pack2(o0, o1);
            }
        }
    }
    __syncthreads();

    // phase L4
    {
        const int tr4 = tid >> 3;
        const int tc4 = tid & 7;
        u64 acc[4] = {0ull, 0ull, 0ull, 0ull};
#pragma unroll 4
        for (int k = 0; k < 128; k++) {
            u64 a = *(const u64*)&f3k[k * S3 + tr4 * 2];
            float4 q = *(const float4*)&W4[k * 32 + tc4 * 4];
            float bv[4] = {q.x, q.y, q.z, q.w};
#pragma unroll
            for (int j = 0; j < 4; j++) fma2(acc[j], a, dup2(bv[j]));
        }
        float4 cb = *(const float4*)(b4 + tc4 * 4);
        float bias0[4] = {cb.x, cb.y, cb.z, cb.w};
#pragma unroll
        for (int j = 0; j < 4; j++) {
            float o0, o1;
            unpack2(acc[j], o0, o1);
            o0 = fmaxf(o0 + bias0[j], 0.f);
            o1 = fmaxf(o1 + bias0[j], 0.f);
            *(u64*)&f4k[(tc4 * 4 + j) * S3 + tr4 * 2] = pack2(o0, o1);
        }
        if (tid < 128) {
            int n = rowBase + tid;
            f4k[32 * S3 + tid] = loc[2 * n];
            f4k[33 * S3 + tid] = loc[2 * n + 1];
            f4k[34 * S3 + tid] = eng[n];
            f4k[35 * S3 + tid] = 0.f;
        }
    }
    __syncthreads();

    // phase gx
    {
        const int rg = tid >> 6;
        const int cg = tid & 63;
        for (int pc = 0; pc < 2; pc++) {
            u64 acc[8][4];
#pragma unroll
            for (int p = 0; p < 8; p++)
#pragma unroll
                for (int j = 0; j < 4; j++) acc[p][j] = 0ull;

#pragma unroll 4
            for (int k = 0; k < 36; k++) {
                const ulonglong2* ap = (const ulonglong2*)(f4k + k * S3 + rg * 16);
                ulonglong2 A0 = ap[0], A1 = ap[1], A2 = ap[2], A3 = ap[3];
                u64 av[8] = {A0.x, A0.y, A1.x, A1.y, A2.x, A2.y, A3.x, A3.y};
                float4 q = *(const float4*)(bsg + k * 516 + pc * 256 + cg * 4);
                float bv[4] = {q.x, q.y, q.z, q.w};
#pragma unroll
                for (int j = 0; j < 4; j++) {
                    u64 bd = dup2(bv[j]);
#pragma unroll
                    for (int p = 0; p < 8; p++) fma2(acc[p][j], av[p], bd);
                }
            }
            float4 cb = *(const float4*)(bg + pc * 256 + cg * 4);
            float bias0[4] = {cb.x, cb.y, cb.z, cb.w};
#pragma unroll
            for (int p = 0; p < 8; p++) {
                int m0 = rowBase + rg * 16 + 2 * p;
                float o0[4], o1[4];
#pragma unroll
                for (int j = 0; j < 4; j++) {
                    unpack2(acc[p][j], o0[j], o1[j]);
                    o0[j] += bias0[j];
                    o1[j] += bias0[j];
                }
                *(float4*)&gx[(size_t)m0 * 512 + pc * 256 + cg * 4] =
                    make_float4(o0[0], o0[1], o0[2], o0[3]);
                *(float4*)&gx[(size_t)(m0 + 1) * 512 + pc * 256 + cg * 4] =
                    make_float4(o1[0], o1[1], o1[2], o1[3]);
            }
        }
    }
}

// ---------------------------------------------------------------------------
// LSTM v4: 16 rows/CTA, 2 barriers/step, mask folded, h streamed to global.
// Heads computed by a separate post-pass kernel.
//   h_s[k][r] transposed with stride 18 (u64-aligned rows, broadcast reads).
//   Per step: [gates(t) + copy-out h_{t-1}] -> sync -> update -> sync.
// ---------------------------------------------------------------------------
#define LROWS 16
#define HS_STR 18

__global__ __launch_bounds__(512) void lstm_v4(
    const float* __restrict__ gx, const int* __restrict__ done,
    const float* __restrict__ h0, const float* __restrict__ c0,
    const float* __restrict__ Whh, float* __restrict__ hs)
{
    extern __shared__ float sm[];
    float* h_s = sm;                       // [HID][HS_STR]  9216 B
    float* gs  = h_s + HID * HS_STR;       // [512][17]      34816 B
    float* msall = gs + 512 * 17;          // [T_LEN*16]     8192 B

    const int tid = threadIdx.x;
    const int r0 = blockIdx.x * LROWS;

    float creg[4];
#pragma unroll
    for (int i = 0; i < 4; i++) {
        int e = tid + i * 512;
        int k = e >> 4, r = e & 15;
        h_s[k * HS_STR + r] = h0[(r0 + r) * HID + k];
        creg[i] = c0[(r0 + r) * HID + k];
    }
#pragma unroll
    for (int i = 0; i < 4; i++) {
        int e = tid + i * 512;
        int t = e >> 4, r = e & 15;
        msall[e] = done[t * B_ENV + r0 + r] ? 0.f : 1.f;
    }
    __syncthreads();

    for (int t = 0; t < T_LEN; t++) {
        // ---- copy-out h_{t-1} (coalesced) — overlaps gates (both read h_s) ----
        if (t > 0) {
#pragma unroll
            for (int i = 0; i < 4; i++) {
                int e = tid + i * 512;
                int k = e & 127, r = e >> 7;
                hs[((size_t)(t - 1) * B_ENV + r0 + r) * HID + k] = h_s[k * HS_STR + r];
            }
        }
        // ---- gates: thread j computes gates[*, j] for 16 rows ----
        {
            u64 macc[8] = {0ull, 0ull, 0ull, 0ull, 0ull, 0ull, 0ull, 0ull};
            const float4* w4 = (const float4*)(Whh + (size_t)tid * HID);
#pragma unroll 8
            for (int kk = 0; kk < 32; kk++) {
                float4 w = w4[kk];
                float wv[4] = {w.x, w.y, w.z, w.w};
#pragma unroll
                for (int s = 0; s < 4; s++) {
                    int k = kk * 4 + s;
                    u64 wd = dup2(wv[s]);
                    const u64* hp = (const u64*)(h_s + k * HS_STR);
                    fma2(macc[0], wd, hp[0]); fma2(macc[1], wd, hp[1]);
                    fma2(macc[2], wd, hp[2]); fma2(macc[3], wd, hp[3]);
                    fma2(macc[4], wd, hp[4]); fma2(macc[5], wd, hp[5]);
                    fma2(macc[6], wd, hp[6]); fma2(macc[7], wd, hp[7]);
                }
            }
            const float* gp = gx + ((size_t)t * B_ENV + r0) * 512 + tid;
            const float* ms = &msall[t * 16];
#pragma unroll
            for (int p = 0; p < 8; p++) {
                u64 gxv = pack2(gp[(size_t)(2 * p) * 512], gp[(size_t)(2 * p + 1) * 512]);
                u64 mp = pack2(ms[2 * p], ms[2 * p + 1]);
                u64 res = fma2o(macc[p], mp, gxv);
                float lo, hi;
                unpack2(res, lo, hi);
                gs[tid * 17 + 2 * p] = lo;
                gs[tid * 17 + 2 * p + 1] = hi;
            }
        }
        __syncthreads();

        // ---- update ----
#pragma unroll
        for (int i = 0; i < 4; i++) {
            int e = tid + i * 512;
            int k = e >> 4, r = e & 15;
            float m = msall[t * 16 + r];
            float ig = gs[k * 17 + r];
            float fg = gs[(HID + k) * 17 + r];
            float gg = gs[(2 * HID + k) * 17 + r];
            float og = gs[(3 * HID + k) * 17 + r];
            float c = sigf(fg) * (creg[i] * m) + sigf(ig) * tanhf(gg);
            creg[i] = c;
            h_s[k * HS_STR + r] = sigf(og) * tanhf(c);
        }
        __syncthreads();
    }

    // final copy-out (t = T_LEN-1)
#pragma unroll
    for (int i = 0; i < 4; i++) {
        int e = tid + i * 512;
        int k = e & 127, r = e >> 7;
        hs[((size_t)(T_LEN - 1) * B_ENV + r0 + r) * HID + k] = h_s[k * HS_STR + r];
    }
}

// ---------------------------------------------------------------------------
// Heads post-pass: out[n, 0:6] = hs[n] @ Wa + ba ; out[n, 6] = hs[n] @ Wc + bc
// ---------------------------------------------------------------------------
__global__ __launch_bounds__(512) void heads_kernel(
    const float* __restrict__ hs,
    const float* __restrict__ Wa, const float* __restrict__ ba,
    const float* __restrict__ Wc, const float* __restrict__ bc,
    float* __restrict__ out)
{
    __shared__ float w[HID * 8];       // [k][c], c: 0..5 Wa, 6 Wc, 7 pad
    __shared__ float bsh[8];

    const int tid = threadIdx.x;
    for (int i = tid; i < HID * 8; i += 512) {
        int k = i >> 3, c = i & 7;
        float v = 0.f;
        if (c < NA) v = Wa[k * NA + c];
        else if (c == NA) v = Wc[k];
        w[i] = v;
    }
    if (tid < 8) bsh[tid] = (tid < NA) ? ba[tid] : ((tid == NA) ? bc[0] : 0.f);
    __syncthreads();

    const size_t n = (size_t)blockIdx.x * 512 + tid;
    const float* hrow = hs + n * HID;
    float acc[7];
#pragma unroll
    for (int c = 0; c < 7; c++) acc[c] = bsh[c];
#pragma unroll 8
    for (int k = 0; k < HID; k += 4) {
        float4 h4 = *(const float4*)(hrow + k);
        float hv[4] = {h4.x, h4.y, h4.z, h4.w};
#pragma unroll
        for (int s = 0; s < 4; s++)
#pragma unroll
            for (int c = 0; c < 7; c++) acc[c] += hv[s] * w[(k + s) * 8 + c];
    }
    float* dst = out + n * 7;
#pragma unroll
    for (int c = 0; c < 7; c++) dst[c] = acc[c];
}

// ---------------------------------------------------------------------------
// Launch
// ---------------------------------------------------------------------------
extern "C" void kernel_launch(void* const* d_in, const int* in_sizes, int n_in,
                              void* d_out, int out_size)
{
    const float* image = (const float*)d_in[0];
    const float* location = (const float*)d_in[1];
    const float* energy = (const float*)d_in[2];
    const int*   done  = (const int*)d_in[3];
    const float* h0 = (const float*)d_in[4];
    const float* c0 = (const float*)d_in[5];
    const float* W1 = (const float*)d_in[6];
    const float* b1 = (const float*)d_in[7];
    const float* W2 = (const float*)d_in[8];
    const float* b2 = (const float*)d_in[9];
    const float* W3 = (const float*)d_in[10];
    const float* b3 = (const float*)d_in[11];
    const float* W4 = (const float*)d_in[12];
    const float* b4 = (const float*)d_in[13];
    const float* Wl = (const float*)d_in[14];
    const float* bl = (const float*)d_in[15];
    const float* We = (const float*)d_in[16];
    const float* be = (const float*)d_in[17];
    const float* Wih = (const float*)d_in[18];
    const float* Whh = (const float*)d_in[19];
    const float* bih = (const float*)d_in[20];
    const float* bhh = (const float*)d_in[21];
    const float* Wa = (const float*)d_in[22];
    const float* ba = (const float*)d_in[23];
    const float* Wc = (const float*)d_in[24];
    const float* bc = (const float*)d_in[25];
    float* out = (float*)d_out;

    float *pf2, *pgx, *pwg, *pbg;
    cudaGetSymbolAddress((void**)&pf2, g_f2);
    cudaGetSymbolAddress((void**)&pgx, g_gx);
    cudaGetSymbolAddress((void**)&pwg, g_wg);
    cudaGetSymbolAddress((void**)&pbg, g_bg);

    prep_wg<<<(36 * 512 + 255) / 256, 256>>>(Wih, Wl, We, pwg);
    prep_bg<<<2, 256>>>(Wih, bl, be, bih, bhh, pbg);

    const int smem12 = (256 * S1 + 26 * S1 + 32 * 264) * 4;
    const int smem345 = (128 * S3 + 36 * S3 + 32 * S3 + 32 * 132 + 36 * 516) * 4;
    const int smemL = (HID * HS_STR + 512 * 17 + T_LEN * 16) * 4;   // 52224 B
    cudaFuncSetAttribute(fused12, cudaFuncAttributeMaxDynamicSharedMemorySize, smem12);
    cudaFuncSetAttribute(fused345, cudaFuncAttributeMaxDynamicSharedMemorySize, smem345);
    cudaFuncSetAttribute(lstm_v4, cudaFuncAttributeMaxDynamicSharedMemorySize, smemL);

    const int MB = N_TOT / 128;   // 4096 row tiles

    fused12<<<MB, 512, smem12>>>(image, W1, b1, W2, b2, pf2);
    fused345<<<MB, 512, smem345>>>(pf2, location, energy, W3, b3, W4, b4, pwg, pbg, pgx);
    // f2 is dead after fused345 — reuse g_f2 as the hs buffer (N x 128).
    lstm_v4<<<B_ENV / LROWS, 512, smemL>>>(pgx, done, h0, c0, Whh, pf2);
    heads_kernel<<<N_TOT / 512, 512>>>(pf2, Wa, ba, Wc, bc, out);
}

// round 11
// speedup vs baseline: 1.6939x; 1.2862x over previous
#include <cuda_runtime.h>
#include <math.h>
#include <stdint.h>

// Problem constants (fixed by the reference)
#define T_LEN 128
#define B_ENV 4096
#define N_TOT (T_LEN * B_ENV)   // 524288
#define HID   128
#define NA    6

// ---------------------------------------------------------------------------
// Scratch (device globals — no runtime allocation allowed)
// ---------------------------------------------------------------------------
__device__ float g_f2[(size_t)N_TOT * 256];   // 512 MB (f2 acts; later reused as hs)
__device__ float g_gx[(size_t)N_TOT * 512];   // 1 GB   precomputed x-gates
__device__ float g_wg[36 * 512];              // combined gx weight, k-major
__device__ float g_bg[512];                   // combined gate bias
__device__ float g_whT[HID * 512];            // Whh transposed: [k][j]

__device__ __forceinline__ float sigf(float x) { return 1.f / (1.f + expf(-x)); }

// ---------------------------------------------------------------------------
// Packed f32x2 helpers
// ---------------------------------------------------------------------------
typedef unsigned long long u64;
__device__ __forceinline__ u64 pack2(float lo, float hi) {
    u64 r; asm("mov.b64 %0, {%1, %2};" : "=l"(r) : "f"(lo), "f"(hi)); return r;
}
__device__ __forceinline__ u64 dup2(float x) {
    u64 r; asm("mov.b64 %0, {%1, %1};" : "=l"(r) : "f"(x)); return r;
}
__device__ __forceinline__ void fma2(u64& acc, u64 a, u64 b) {
    asm("fma.rn.f32x2 %0, %1, %2, %0;" : "+l"(acc) : "l"(a), "l"(b));
}
__device__ __forceinline__ u64 fma2o(u64 a, u64 b, u64 c) {
    u64 r; asm("fma.rn.f32x2 %0, %1, %2, %3;" : "=l"(r) : "l"(a), "l"(b), "l"(c));
    return r;
}
__device__ __forceinline__ void unpack2(u64 v, float& lo, float& hi) {
    asm("mov.b64 {%0, %1}, %2;" : "=f"(lo), "=f"(hi) : "l"(v));
}

// ---------------------------------------------------------------------------
// Weight prep
// ---------------------------------------------------------------------------
__global__ void prep_wg(const float* __restrict__ Wih, const float* __restrict__ Wl,
                        const float* __restrict__ We, float* __restrict__ out)
{
    int idx = blockIdx.x * 256 + threadIdx.x;
    if (idx >= 36 * 512) return;
    int k = idx >> 9, n = idx & 511;
    float v = 0.f;
    if (k < 32) {
        v = Wih[n * 96 + k];
    } else if (k < 34) {
        int d = k - 32;
        float s = 0.f;
        for (int j = 0; j < 32; j++) s += Wl[d * 32 + j] * Wih[n * 96 + 32 + j];
        v = s * 0.1f;
    } else if (k == 34) {
        float s = 0.f;
        for (int j = 0; j < 32; j++) s += We[j] * Wih[n * 96 + 64 + j];
        v = s * (1.f / 200.f);
    }
    out[k * 512 + n] = v;
}

__global__ void prep_bg(const float* __restrict__ Wih, const float* __restrict__ bl,
                        const float* __restrict__ be, const float* __restrict__ bih,
                        const float* __restrict__ bhh, float* __restrict__ bg)
{
    int n = blockIdx.x * 256 + threadIdx.x;
    if (n >= 512) return;
    float s = bih[n] + bhh[n];
    for (int j = 0; j < 32; j++)
        s += bl[j] * Wih[n * 96 + 32 + j] + be[j] * Wih[n * 96 + 64 + j];
    bg[n] = s;
}

// Transpose Whh [512][128] -> whT [128][512]
__global__ void prep_whT(const float* __restrict__ Whh, float* __restrict__ whT)
{
    int idx = blockIdx.x * 256 + threadIdx.x;
    if (idx >= HID * 512) return;
    int k = idx >> 9, j = idx & 511;
    whT[idx] = Whh[j * HID + k];
}

// ---------------------------------------------------------------------------
// Fused L1+L2 (unchanged from R10)
// ---------------------------------------------------------------------------
#define S1 132

__global__ __launch_bounds__(512) void fused12(
    const float* __restrict__ img, const float* __restrict__ W1,
    const float* __restrict__ b1, const float* __restrict__ W2,
    const float* __restrict__ b2, float* __restrict__ f2)
{
    extern __shared__ float sm[];
    float* f1k = sm;                     // [256][S1]
    float* xsk = f1k + 256 * S1;         // [26][S1]
    float* bs  = xsk + 26 * S1;          // [32][264] double-buffered B

    const int tid = threadIdx.x;
    const int rg = tid >> 6;
    const int cg = tid & 63;
    const int rowBase = blockIdx.x * 128;

    for (int i = tid; i < 128 * 25; i += 512) {
        int k = i % 25, m = i / 25;
        xsk[k * S1 + m] = img[(size_t)(rowBase + m) * 25 + k] * (1.f / 255.f);
    }
    for (int i = tid; i < 25 * 256; i += 512) {
        int k = i >> 8, n = i & 255;
        bs[k * 264 + n] = W1[i];
    }
    __syncthreads();

    u64 acc[8][4];
#pragma unroll
    for (int p = 0; p < 8; p++)
#pragma unroll
        for (int j = 0; j < 4; j++) acc[p][j] = 0ull;

    for (int k = 0; k < 25; k++) {
        const ulonglong2* ap = (const ulonglong2*)(xsk + k * S1 + rg * 16);
        ulonglong2 A0 = ap[0], A1 = ap[1], A2 = ap[2], A3 = ap[3];
        u64 av[8] = {A0.x, A0.y, A1.x, A1.y, A2.x, A2.y, A3.x, A3.y};
        float4 q = *(const float4*)(bs + k * 264 + cg * 4);
        float bv[4] = {q.x, q.y, q.z, q.w};
#pragma unroll
        for (int j = 0; j < 4; j++) {
            u64 bd = dup2(bv[j]);
#pragma unroll
            for (int p = 0; p < 8; p++) fma2(acc[p][j], av[p], bd);
        }
    }
    {
        float4 c1 = *(const float4*)(b1 + cg * 4);
        float bias1[4] = {c1.x, c1.y, c1.z, c1.w};
#pragma unroll
        for (int p = 0; p < 8; p++) {
            int m0 = rg * 16 + 2 * p;
#pragma unroll
            for (int j = 0; j < 4; j++) {
                float o0, o1;
                unpack2(acc[p][j], o0, o1);
                o0 = fmaxf(o0 + bias1[j], 0.f);
                o1 = fmaxf(o1 + bias1[j], 0.f);
                *(u64*)&f1k[(cg * 4 + j) * S1 + m0] = pack2(o0, o1);
            }
        }
    }

    float ldr[8];
#define LOADW2(c)                                                      \
    _Pragma("unroll") for (int i = 0; i < 8; i++) {                    \
        int idx = tid + i * 512;                                       \
        int k = idx >> 8, n = idx & 255;                               \
        ldr[i] = W2[(size_t)((c) * 16 + k) * 256 + n];                 \
    }
#define STW2(buf)                                                      \
    _Pragma("unroll") for (int i = 0; i < 8; i++) {                    \
        int idx = tid + i * 512;                                       \
        int k = idx >> 8, n = idx & 255;                               \
        bs[((buf) * 16 + k) * 264 + n] = ldr[i];                       \
    }

    LOADW2(0);
    __syncthreads();
    STW2(0);
    __syncthreads();

#pragma unroll
    for (int p = 0; p < 8; p++)
#pragma unroll
        for (int j = 0; j < 4; j++) acc[p][j] = 0ull;

    for (int c = 0; c < 16; c++) {
        if (c < 15) { LOADW2(c + 1); }
        const float* bsc = bs + (c & 1) * 16 * 264;
        const float* f1c = f1k + c * 16 * S1;
#pragma unroll
        for (int k = 0; k < 16; k++) {
            const ulonglong2* ap = (const ulonglong2*)(f1c + k * S1 + rg * 16);
            ulonglong2 A0 = ap[0], A1 = ap[1], A2 = ap[2], A3 = ap[3];
            u64 av[8] = {A0.x, A0.y, A1.x, A1.y, A2.x, A2.y, A3.x, A3.y};
            float4 q = *(const float4*)(bsc + k * 264 + cg * 4);
            float bv[4] = {q.x, q.y, q.z, q.w};
#pragma unroll
            for (int j = 0; j < 4; j++) {
                u64 bd = dup2(bv[j]);
#pragma unroll
                for (int p = 0; p < 8; p++) fma2(acc[p][j], av[p], bd);
            }
        }
        if (c < 15) { STW2((c + 1) & 1); }
        __syncthreads();
    }
#undef LOADW2
#undef STW2

    {
        float4 c2 = *(const float4*)(b2 + cg * 4);
        float bias2[4] = {c2.x, c2.y, c2.z, c2.w};
#pragma unroll
        for (int p = 0; p < 8; p++) {
            int m0 = rowBase + rg * 16 + 2 * p;
            float o0[4], o1[4];
#pragma unroll
            for (int j = 0; j < 4; j++) {
                unpack2(acc[p][j], o0[j], o1[j]);
                o0[j] = fmaxf(o0[j] + bias2[j], 0.f);
                o1[j] = fmaxf(o1[j] + bias2[j], 0.f);
            }
            *(float4*)&f2[(size_t)m0 * 256 + cg * 4] =
                make_float4(o0[0], o0[1], o0[2], o0[3]);
            *(float4*)&f2[(size_t)(m0 + 1) * 256 + cg * 4] =
                make_float4(o1[0], o1[1], o1[2], o1[3]);
        }
    }
}

// ---------------------------------------------------------------------------
// Fused L3+L4+loc/eng+gx (unchanged from R10)
// ---------------------------------------------------------------------------
#define S3 132

__global__ __launch_bounds__(512) void fused345(
    const float* __restrict__ f2, const float* __restrict__ loc,
    const float* __restrict__ eng,
    const float* __restrict__ W3, const float* __restrict__ b3,
    const float* __restrict__ W4, const float* __restrict__ b4,
    const float* __restrict__ wg, const float* __restrict__ bg,
    float* __restrict__ gx)
{
    extern __shared__ float sm[];
    float* f3k = sm;                      // [128][S3]
    float* f4k = f3k + 128 * S3;          // [36][S3]
    float* as2 = f4k + 36 * S3;           // 2 x [16][S3]
    float* bs3 = as2 + 32 * S3;           // 2 x [16][132]
    float* bsg = bs3 + 32 * 132;          // [36][516]

    const int tid = threadIdx.x;
    const int rowBase = blockIdx.x * 128;

    for (int i = tid; i < 36 * 512; i += 512) {
        int k = i >> 9, n = i & 511;
        bsg[k * 516 + n] = wg[i];
    }

    // phase L3
    {
        const int rg = tid >> 5;
        const int cg = tid & 31;
        u64 acc[4][4];
#pragma unroll
        for (int p = 0; p < 4; p++)
#pragma unroll
            for (int j = 0; j < 4; j++) acc[p][j] = 0ull;

        float lA[4], lB[4];
#define LD3(c)                                                         \
    _Pragma("unroll") for (int i = 0; i < 4; i++) {                    \
        int idx = tid + i * 512;                                       \
        int ka = idx & 15, ma = idx >> 4;                              \
        lA[i] = f2[(size_t)(rowBase + ma) * 256 + (c) * 16 + ka];      \
        int nb = idx & 127, kb = idx >> 7;                             \
        lB[i] = W3[(size_t)((c) * 16 + kb) * 128 + nb];                \
    }
#define ST3(buf)                                                       \
    _Pragma("unroll") for (int i = 0; i < 4; i++) {                    \
        int idx = tid + i * 512;                                       \
        int ka = idx & 15, ma = idx >> 4;                              \
        as2[((buf) * 16 + ka) * S3 + ma] = lA[i];                      \
        int nb = idx & 127, kb = idx >> 7;                             \
        bs3[((buf) * 16 + kb) * 132 + nb] = lB[i];                     \
    }
        LD3(0); ST3(0);
        __syncthreads();
        for (int c = 0; c < 16; c++) {
            if (c < 15) { LD3(c + 1); }
            const float* ab = as2 + (c & 1) * 16 * S3;
            const float* bb = bs3 + (c & 1) * 16 * 132;
#pragma unroll
            for (int k = 0; k < 16; k++) {
                const ulonglong2* ap = (const ulonglong2*)(ab + k * S3 + rg * 8);
                ulonglong2 A0 = ap[0], A1 = ap[1];
                u64 av[4] = {A0.x, A0.y, A1.x, A1.y};
                float4 q = *(const float4*)(bb + k * 132 + cg * 4);
                float bv[4] = {q.x, q.y, q.z, q.w};
#pragma unroll
                for (int j = 0; j < 4; j++) {
                    u64 bd = dup2(bv[j]);
#pragma unroll
                    for (int p = 0; p < 4; p++) fma2(acc[p][j], av[p], bd);
                }
            }
            if (c < 15) { ST3((c + 1) & 1); }
            __syncthreads();
        }
#undef LD3
#undef ST3
        float4 cb = *(const float4*)(b3 + cg * 4);
        float bias0[4] = {cb.x, cb.y, cb.z, cb.w};
#pragma unroll
        for (int p = 0; p < 4; p++) {
            int m0 = rg * 8 + 2 * p;
#pragma unroll
            for (int j = 0; j < 4; j++) {
                float o0, o1;
                unpack2(acc[p][j], o0, o1);
                o0 = fmaxf(o0 + bias0[j], 0.f);
                o1 = fmaxf(o1 + bias0[j], 0.f);
                *(u64*)&f3k[(cg * 4 + j) * S3 + m0] = pack2(o0, o1);
            }
        }
    }
    __syncthreads();

    // phase L4
    {
        const int tr4 = tid >> 3;
        const int tc4 = tid & 7;
        u64 acc[4] = {0ull, 0ull, 0ull, 0ull};
#pragma unroll 4
        for (int k = 0; k < 128; k++) {
            u64 a = *(const u64*)&f3k[k * S3 + tr4 * 2];
            float4 q = *(const float4*)&W4[k * 32 + tc4 * 4];
            float bv[4] = {q.x, q.y, q.z, q.w};
#pragma unroll
            for (int j = 0; j < 4; j++) fma2(acc[j], a, dup2(bv[j]));
        }
        float4 cb = *(const float4*)(b4 + tc4 * 4);
        float bias0[4] = {cb.x, cb.y, cb.z, cb.w};
#pragma unroll
        for (int j = 0; j < 4; j++) {
            float o0, o1;
            unpack2(acc[j], o0, o1);
            o0 = fmaxf(o0 + bias0[j], 0.f);
            o1 = fmaxf(o1 + bias0[j], 0.f);
            *(u64*)&f4k[(tc4 * 4 + j) * S3 + tr4 * 2] = pack2(o0, o1);
        }
        if (tid < 128) {
            int n = rowBase + tid;
            f4k[32 * S3 + tid] = loc[2 * n];
            f4k[33 * S3 + tid] = loc[2 * n + 1];
            f4k[34 * S3 + tid] = eng[n];
            f4k[35 * S3 + tid] = 0.f;
        }
    }
    __syncthreads();

    // phase gx
    {
        const int rg = tid >> 6;
        const int cg = tid & 63;
        for (int pc = 0; pc < 2; pc++) {
            u64 acc[8][4];
#pragma unroll
            for (int p = 0; p < 8; p++)
#pragma unroll
                for (int j = 0; j < 4; j++) acc[p][j] = 0ull;

#pragma unroll 4
            for (int k = 0; k < 36; k++) {
                const ulonglong2* ap = (const ulonglong2*)(f4k + k * S3 + rg * 16);
                ulonglong2 A0 = ap[0], A1 = ap[1], A2 = ap[2], A3 = ap[3];
                u64 av[8] = {A0.x, A0.y, A1.x, A1.y, A2.x, A2.y, A3.x, A3.y};
                float4 q = *(const float4*)(bsg + k * 516 + pc * 256 + cg * 4);
                float bv[4] = {q.x, q.y, q.z, q.w};
#pragma unroll
                for (int j = 0; j < 4; j++) {
                    u64 bd = dup2(bv[j]);
#pragma unroll
                    for (int p = 0; p < 8; p++) fma2(acc[p][j], av[p], bd);
                }
            }
            float4 cb = *(const float4*)(bg + pc * 256 + cg * 4);
            float bias0[4] = {cb.x, cb.y, cb.z, cb.w};
#pragma unroll
            for (int p = 0; p < 8; p++) {
                int m0 = rowBase + rg * 16 + 2 * p;
                float o0[4], o1[4];
#pragma unroll
                for (int j = 0; j < 4; j++) {
                    unpack2(acc[p][j], o0[j], o1[j]);
                    o0[j] += bias0[j];
                    o1[j] += bias0[j];
                }
                *(float4*)&gx[(size_t)m0 * 512 + pc * 256 + cg * 4] =
                    make_float4(o0[0], o0[1], o0[2], o0[3]);
                *(float4*)&gx[(size_t)(m0 + 1) * 512 + pc * 256 + cg * 4] =
                    make_float4(o1[0], o1[1], o1[2], o1[3]);
            }
        }
    }
}

// ---------------------------------------------------------------------------
// LSTM v5: 32 rows/CTA (128 CTAs -> 1/SM), coalesced WhhT, gx prefetch,
// 2 barriers/step, mask folded, h streamed to global; heads post-pass.
// ---------------------------------------------------------------------------
#define LROWS 32
#define HS_STR 36   // floats; 36*4=144 B, 16B-aligned rows for ulonglong2
#define GS_STR 34   // floats; 34*4=136 B, 8B-aligned u64 stores

__global__ __launch_bounds__(512) void lstm_v5(
    const float* __restrict__ gx, const int* __restrict__ done,
    const float* __restrict__ h0, const float* __restrict__ c0,
    const float* __restrict__ whT, float* __restrict__ hs)
{
    extern __shared__ float sm[];
    float* h_s = sm;                        // [HID][HS_STR]   18432 B
    float* gs  = h_s + HID * HS_STR;        // [512][GS_STR]   69632 B
    float* msall = gs + 512 * GS_STR;       // [T_LEN*32]      16384 B

    const int tid = threadIdx.x;
    const int r0 = blockIdx.x * LROWS;

    float creg[8];
#pragma unroll
    for (int i = 0; i < 8; i++) {
        int e = tid + i * 512;
        int k = e >> 5, r = e & 31;
        h_s[k * HS_STR + r] = h0[(r0 + r) * HID + k];
        creg[i] = c0[(r0 + r) * HID + k];
    }
#pragma unroll
    for (int i = 0; i < 8; i++) {
        int e = tid + i * 512;
        int t = e >> 5, r = e & 31;
        msall[e] = done[t * B_ENV + r0 + r] ? 0.f : 1.f;
    }
    __syncthreads();

    for (int t = 0; t < T_LEN; t++) {
        // ---- prefetch gx for this step (latency hidden under matvec) ----
        const float* gp = gx + ((size_t)t * B_ENV + r0) * 512 + tid;
        u64 gxp[16];
#pragma unroll
        for (int p = 0; p < 16; p++)
            gxp[p] = pack2(gp[(size_t)(2 * p) * 512], gp[(size_t)(2 * p + 1) * 512]);

        // ---- copy-out h_{t-1} (coalesced) ----
        if (t > 0) {
#pragma unroll
            for (int i = 0; i < 8; i++) {
                int e = tid + i * 512;
                int k = e & 127, r = e >> 7;
                hs[((size_t)(t - 1) * B_ENV + r0 + r) * HID + k] = h_s[k * HS_STR + r];
            }
        }

        // ---- gates: thread j = tid computes gates[*, j] for 32 rows ----
        {
            u64 macc[16];
#pragma unroll
            for (int p = 0; p < 16; p++) macc[p] = 0ull;

            const float* wp = whT + tid;
#pragma unroll 4
            for (int k = 0; k < HID; k++) {
                u64 wd = dup2(wp[(size_t)k * 512]);
                const ulonglong2* hp = (const ulonglong2*)(h_s + k * HS_STR);
                ulonglong2 H0 = hp[0], H1 = hp[1], H2 = hp[2], H3 = hp[3];
                ulonglong2 H4 = hp[4], H5 = hp[5], H6 = hp[6], H7 = hp[7];
                fma2(macc[0], wd, H0.x);  fma2(macc[1], wd, H0.y);
                fma2(macc[2], wd, H1.x);  fma2(macc[3], wd, H1.y);
                fma2(macc[4], wd, H2.x);  fma2(macc[5], wd, H2.y);
                fma2(macc[6], wd, H3.x);  fma2(macc[7], wd, H3.y);
                fma2(macc[8], wd, H4.x);  fma2(macc[9], wd, H4.y);
                fma2(macc[10], wd, H5.x); fma2(macc[11], wd, H5.y);
                fma2(macc[12], wd, H6.x); fma2(macc[13], wd, H6.y);
                fma2(macc[14], wd, H7.x); fma2(macc[15], wd, H7.y);
            }
            const float* ms = &msall[t * 32];
#pragma unroll
            for (int p = 0; p < 16; p++) {
                u64 mp = pack2(ms[2 * p], ms[2 * p + 1]);
                *(u64*)&gs[tid * GS_STR + 2 * p] = fma2o(macc[p], mp, gxp[p]);
            }
        }
        __syncthreads();

        // ---- update ----
#pragma unroll
        for (int i = 0; i < 8; i++) {
            int e = tid + i * 512;
            int k = e >> 5, r = e & 31;
            float m = msall[t * 32 + r];
            float ig = gs[k * GS_STR + r];
            float fg = gs[(HID + k) * GS_STR + r];
            float gg = gs[(2 * HID + k) * GS_STR + r];
            float og = gs[(3 * HID + k) * GS_STR + r];
            float c = sigf(fg) * (creg[i] * m) + sigf(ig) * tanhf(gg);
            creg[i] = c;
            h_s[k * HS_STR + r] = sigf(og) * tanhf(c);
        }
        __syncthreads();
    }

    // final copy-out (t = T_LEN-1)
#pragma unroll
    for (int i = 0; i < 8; i++) {
        int e = tid + i * 512;
        int k = e & 127, r = e >> 7;
        hs[((size_t)(T_LEN - 1) * B_ENV + r0 + r) * HID + k] = h_s[k * HS_STR + r];
    }
}

// ---------------------------------------------------------------------------
// Heads post-pass: out[n, 0:6] = hs[n] @ Wa + ba ; out[n, 6] = hs[n] @ Wc + bc
// ---------------------------------------------------------------------------
__global__ __launch_bounds__(512) void heads_kernel(
    const float* __restrict__ hs,
    const float* __restrict__ Wa, const float* __restrict__ ba,
    const float* __restrict__ Wc, const float* __restrict__ bc,
    float* __restrict__ out)
{
    __shared__ float w[HID * 8];
    __shared__ float bsh[8];

    const int tid = threadIdx.x;
    for (int i = tid; i < HID * 8; i += 512) {
        int k = i >> 3, c = i & 7;
        float v = 0.f;
        if (c < NA) v = Wa[k * NA + c];
        else if (c == NA) v = Wc[k];
        w[i] = v;
    }
    if (tid < 8) bsh[tid] = (tid < NA) ? ba[tid] : ((tid == NA) ? bc[0] : 0.f);
    __syncthreads();

    const size_t n = (size_t)blockIdx.x * 512 + tid;
    const float* hrow = hs + n * HID;
    float acc[7];
#pragma unroll
    for (int c = 0; c < 7; c++) acc[c] = bsh[c];
#pragma unroll 8
    for (int k = 0; k < HID; k += 4) {
        float4 h4 = *(const float4*)(hrow + k);
        float hv[4] = {h4.x, h4.y, h4.z, h4.w};
#pragma unroll
        for (int s = 0; s < 4; s++)
#pragma unroll
            for (int c = 0; c < 7; c++) acc[c] += hv[s] * w[(k + s) * 8 + c];
    }
    float* dst = out + n * 7;
#pragma unroll
    for (int c = 0; c < 7; c++) dst[c] = acc[c];
}

// ---------------------------------------------------------------------------
// Launch
// ---------------------------------------------------------------------------
extern "C" void kernel_launch(void* const* d_in, const int* in_sizes, int n_in,
                              void* d_out, int out_size)
{
    const float* image = (const float*)d_in[0];
    const float* location = (const float*)d_in[1];
    const float* energy = (const float*)d_in[2];
    const int*   done  = (const int*)d_in[3];
    const float* h0 = (const float*)d_in[4];
    const float* c0 = (const float*)d_in[5];
    const float* W1 = (const float*)d_in[6];
    const float* b1 = (const float*)d_in[7];
    const float* W2 = (const float*)d_in[8];
    const float* b2 = (const float*)d_in[9];
    const float* W3 = (const float*)d_in[10];
    const float* b3 = (const float*)d_in[11];
    const float* W4 = (const float*)d_in[12];
    const float* b4 = (const float*)d_in[13];
    const float* Wl = (const float*)d_in[14];
    const float* bl = (const float*)d_in[15];
    const float* We = (const float*)d_in[16];
    const float* be = (const float*)d_in[17];
    const float* Wih = (const float*)d_in[18];
    const float* Whh = (const float*)d_in[19];
    const float* bih = (const float*)d_in[20];
    const float* bhh = (const float*)d_in[21];
    const float* Wa = (const float*)d_in[22];
    const float* ba = (const float*)d_in[23];
    const float* Wc = (const float*)d_in[24];
    const float* bc = (const float*)d_in[25];
    float* out = (float*)d_out;

    float *pf2, *pgx, *pwg, *pbg, *pwhT;
    cudaGetSymbolAddress((void**)&pf2, g_f2);
    cudaGetSymbolAddress((void**)&pgx, g_gx);
    cudaGetSymbolAddress((void**)&pwg, g_wg);
    cudaGetSymbolAddress((void**)&pbg, g_bg);
    cudaGetSymbolAddress((void**)&pwhT, g_whT);

    prep_wg<<<(36 * 512 + 255) / 256, 256>>>(Wih, Wl, We, pwg);
    prep_bg<<<2, 256>>>(Wih, bl, be, bih, bhh, pbg);
    prep_whT<<<(HID * 512 + 255) / 256, 256>>>(Whh, pwhT);

    const int smem12 = (256 * S1 + 26 * S1 + 32 * 264) * 4;
    const int smem345 = (128 * S3 + 36 * S3 + 32 * S3 + 32 * 132 + 36 * 516) * 4;
    const int smemL = (HID * HS_STR + 512 * GS_STR + T_LEN * 32) * 4;   // 104448 B
    cudaFuncSetAttribute(fused12, cudaFuncAttributeMaxDynamicSharedMemorySize, smem12);
    cudaFuncSetAttribute(fused345, cudaFuncAttributeMaxDynamicSharedMemorySize, smem345);
    cudaFuncSetAttribute(lstm_v5, cudaFuncAttributeMaxDynamicSharedMemorySize, smemL);

    const int MB = N_TOT / 128;   // 4096 row tiles

    fused12<<<MB, 512, smem12>>>(image, W1, b1, W2, b2, pf2);
    fused345<<<MB, 512, smem345>>>(pf2, location, energy, W3, b3, W4, b4, pwg, pbg, pgx);
    // f2 is dead after fused345 — reuse g_f2 as the hs buffer (N x 128).
    lstm_v5<<<B_ENV / LROWS, 512, smemL>>>(pgx, done, h0, c0, pwhT, pf2);
    heads_kernel<<<N_TOT / 512, 512>>>(pf2, Wa, ba, Wc, bc, out);
}

// round 12
// speedup vs baseline: 1.7768x; 1.0489x over previous
#include <cuda_runtime.h>
#include <math.h>
#include <stdint.h>

// Problem constants (fixed by the reference)
#define T_LEN 128
#define B_ENV 4096
#define N_TOT (T_LEN * B_ENV)   // 524288
#define HID   128
#define NA    6

// ---------------------------------------------------------------------------
// Scratch (device globals — no runtime allocation allowed)
// ---------------------------------------------------------------------------
__device__ float g_hs[(size_t)N_TOT * 128];   // 256 MB  hidden states
__device__ float g_gx[(size_t)N_TOT * 512];   // 1 GB    precomputed x-gates
__device__ float g_wg[36 * 512];              // combined gx weight, k-major
__device__ float g_bg[512];                   // combined gate bias
__device__ float g_whT[HID * 512];            // Whh transposed: [k][j]

// ---------------------------------------------------------------------------
// Packed f32x2 helpers
// ---------------------------------------------------------------------------
typedef unsigned long long u64;
__device__ __forceinline__ u64 pack2(float lo, float hi) {
    u64 r; asm("mov.b64 %0, {%1, %2};" : "=l"(r) : "f"(lo), "f"(hi)); return r;
}
__device__ __forceinline__ u64 dup2(float x) {
    u64 r; asm("mov.b64 %0, {%1, %1};" : "=l"(r) : "f"(x)); return r;
}
__device__ __forceinline__ void fma2(u64& acc, u64 a, u64 b) {
    asm("fma.rn.f32x2 %0, %1, %2, %0;" : "+l"(acc) : "l"(a), "l"(b));
}
__device__ __forceinline__ u64 fma2o(u64 a, u64 b, u64 c) {
    u64 r; asm("fma.rn.f32x2 %0, %1, %2, %3;" : "=l"(r) : "l"(a), "l"(b), "l"(c));
    return r;
}
__device__ __forceinline__ void unpack2(u64 v, float& lo, float& hi) {
    asm("mov.b64 {%0, %1}, %2;" : "=f"(lo), "=f"(hi) : "l"(v));
}
// Hardware tanh (MUFU.TANH, sm_75+ base ISA)
__device__ __forceinline__ float ftanh(float x) {
    float y; asm("tanh.approx.f32 %0, %1;" : "=f"(y) : "f"(x)); return y;
}
__device__ __forceinline__ float fsig(float x) {
    return fmaf(0.5f, ftanh(0.5f * x), 0.5f);
}

// ---------------------------------------------------------------------------
// Weight prep
// ---------------------------------------------------------------------------
__global__ void prep_wg(const float* __restrict__ Wih, const float* __restrict__ Wl,
                        const float* __restrict__ We, float* __restrict__ out)
{
    int idx = blockIdx.x * 256 + threadIdx.x;
    if (idx >= 36 * 512) return;
    int k = idx >> 9, n = idx & 511;
    float v = 0.f;
    if (k < 32) {
        v = Wih[n * 96 + k];
    } else if (k < 34) {
        int d = k - 32;
        float s = 0.f;
        for (int j = 0; j < 32; j++) s += Wl[d * 32 + j] * Wih[n * 96 + 32 + j];
        v = s * 0.1f;
    } else if (k == 34) {
        float s = 0.f;
        for (int j = 0; j < 32; j++) s += We[j] * Wih[n * 96 + 64 + j];
        v = s * (1.f / 200.f);
    }
    out[k * 512 + n] = v;
}

__global__ void prep_bg(const float* __restrict__ Wih, const float* __restrict__ bl,
                        const float* __restrict__ be, const float* __restrict__ bih,
                        const float* __restrict__ bhh, float* __restrict__ bg)
{
    int n = blockIdx.x * 256 + threadIdx.x;
    if (n >= 512) return;
    float s = bih[n] + bhh[n];
    for (int j = 0; j < 32; j++)
        s += bl[j] * Wih[n * 96 + 32 + j] + be[j] * Wih[n * 96 + 64 + j];
    bg[n] = s;
}

__global__ void prep_whT(const float* __restrict__ Whh, float* __restrict__ whT)
{
    int idx = blockIdx.x * 256 + threadIdx.x;
    if (idx >= HID * 512) return;
    int k = idx >> 9, j = idx & 511;
    whT[idx] = Whh[j * HID + k];
}

// ---------------------------------------------------------------------------
// MEGA encoder: image -> f1 -> f2 -> f3 -> f4(+loc/eng) -> gx, ONE kernel.
// 128-row tile per CTA; all intermediates stay in SMEM (k-major).
// ---------------------------------------------------------------------------
#define SS 132   // k-major row stride (132*4=528 B, 16B-aligned)

__global__ __launch_bounds__(512) void mega_enc(
    const float* __restrict__ img, const float* __restrict__ loc,
    const float* __restrict__ eng,
    const float* __restrict__ W1, const float* __restrict__ b1,
    const float* __restrict__ W2, const float* __restrict__ b2,
    const float* __restrict__ W3, const float* __restrict__ b3,
    const float* __restrict__ W4, const float* __restrict__ b4,
    const float* __restrict__ wg, const float* __restrict__ bg,
    float* __restrict__ gx)
{
    extern __shared__ float sm[];
    float* fA   = sm;                    // [256][SS] : f1, then f2, then f3(cols<128)
    float* faux = fA + 256 * SS;         // [36][SS]  : xsk (25 rows), later f4
    float* bs   = faux + 36 * SS;        // [32][264] : W staging (double-buffered)

    const int tid = threadIdx.x;
    const int rowBase = blockIdx.x * 128;

    // ---- stage image (k-major, scaled) + full W1 ----
    for (int i = tid; i < 128 * 25; i += 512) {
        int k = i % 25, m = i / 25;
        faux[k * SS + m] = img[(size_t)(rowBase + m) * 25 + k] * (1.f / 255.f);
    }
    for (int i = tid; i < 25 * 256; i += 512) {
        int k = i >> 8, n = i & 255;
        bs[k * 264 + n] = W1[i];
    }
    __syncthreads();

    // ================= phase 1: f1 = relu(x @ W1 + b1), K=25 =================
    {
        const int rg = tid >> 6;         // 8 groups x 16 rows
        const int cg = tid & 63;         // x4 cols
        u64 acc[8][4];
#pragma unroll
        for (int p = 0; p < 8; p++)
#pragma unroll
            for (int j = 0; j < 4; j++) acc[p][j] = 0ull;

        for (int k = 0; k < 25; k++) {
            const ulonglong2* ap = (const ulonglong2*)(faux + k * SS + rg * 16);
            ulonglong2 A0 = ap[0], A1 = ap[1], A2 = ap[2], A3 = ap[3];
            u64 av[8] = {A0.x, A0.y, A1.x, A1.y, A2.x, A2.y, A3.x, A3.y};
            float4 q = *(const float4*)(bs + k * 264 + cg * 4);
            float bv[4] = {q.x, q.y, q.z, q.w};
#pragma unroll
            for (int j = 0; j < 4; j++) {
                u64 bd = dup2(bv[j]);
#pragma unroll
                for (int p = 0; p < 8; p++) fma2(acc[p][j], av[p], bd);
            }
        }
        float4 c1 = *(const float4*)(b1 + cg * 4);
        float bias1[4] = {c1.x, c1.y, c1.z, c1.w};
        __syncthreads();   // xsk reads done before fA writes? (fA untouched; bar for W staging order)
#pragma unroll
        for (int p = 0; p < 8; p++) {
            int m0 = rg * 16 + 2 * p;
#pragma unroll
            for (int j = 0; j < 4; j++) {
                float o0, o1;
                unpack2(acc[p][j], o0, o1);
                o0 = fmaxf(o0 + bias1[j], 0.f);
                o1 = fmaxf(o1 + bias1[j], 0.f);
                *(u64*)&fA[(cg * 4 + j) * SS + m0] = pack2(o0, o1);
            }
        }
    }

    // ================= phase 2: f2 = relu(f1 @ W2 + b2), K=256 ================
    {
        const int rg = tid >> 6;
        const int cg = tid & 63;
        float ldr[8];
#define LOADW2(c)                                                      \
    _Pragma("unroll") for (int i = 0; i < 8; i++) {                    \
        int idx = tid + i * 512;                                       \
        int k = idx >> 8, n = idx & 255;                               \
        ldr[i] = W2[(size_t)((c) * 16 + k) * 256 + n];                 \
    }
#define STW2(buf)                                                      \
    _Pragma("unroll") for (int i = 0; i < 8; i++) {                    \
        int idx = tid + i * 512;                                       \
        int k = idx >> 8, n = idx & 255;                               \
        bs[((buf) * 16 + k) * 264 + n] = ldr[i];                       \
    }
        LOADW2(0);
        __syncthreads();   // f1 writes complete; bs(W1) no longer needed
        STW2(0);
        __syncthreads();

        u64 acc[8][4];
#pragma unroll
        for (int p = 0; p < 8; p++)
#pragma unroll
            for (int j = 0; j < 4; j++) acc[p][j] = 0ull;

        for (int c = 0; c < 16; c++) {
            if (c < 15) { LOADW2(c + 1); }
            const float* bsc = bs + (c & 1) * 16 * 264;
            const float* f1c = fA + c * 16 * SS;
#pragma unroll
            for (int k = 0; k < 16; k++) {
                const ulonglong2* ap = (const ulonglong2*)(f1c + k * SS + rg * 16);
                ulonglong2 A0 = ap[0], A1 = ap[1], A2 = ap[2], A3 = ap[3];
                u64 av[8] = {A0.x, A0.y, A1.x, A1.y, A2.x, A2.y, A3.x, A3.y};
                float4 q = *(const float4*)(bsc + k * 264 + cg * 4);
                float bv[4] = {q.x, q.y, q.z, q.w};
#pragma unroll
                for (int j = 0; j < 4; j++) {
                    u64 bd = dup2(bv[j]);
#pragma unroll
                    for (int p = 0; p < 8; p++) fma2(acc[p][j], av[p], bd);
                }
            }
            if (c < 15) { STW2((c + 1) & 1); }
            __syncthreads();
        }
#undef LOADW2
#undef STW2
        // overwrite fA with f2 (k-major); last sync above ensures reads done
        float4 c2 = *(const float4*)(b2 + cg * 4);
        float bias2[4] = {c2.x, c2.y, c2.z, c2.w};
#pragma unroll
        for (int p = 0; p < 8; p++) {
            int m0 = rg * 16 + 2 * p;
#pragma unroll
            for (int j = 0; j < 4; j++) {
                float o0, o1;
                unpack2(acc[p][j], o0, o1);
                o0 = fmaxf(o0 + bias2[j], 0.f);
                o1 = fmaxf(o1 + bias2[j], 0.f);
                *(u64*)&fA[(cg * 4 + j) * SS + m0] = pack2(o0, o1);
            }
        }
    }
    __syncthreads();

    // ================= phase 3: f3 = relu(f2 @ W3 + b3), K=256 ================
    {
        const int rg = tid >> 5;         // 16 groups x 8 rows
        const int cg = tid & 31;         // x4 cols
        float ldr[4];
#define LOADW3(c)                                                      \
    _Pragma("unroll") for (int i = 0; i < 4; i++) {                    \
        int idx = tid + i * 512;                                       \
        int k = idx >> 7, n = idx & 127;                               \
        ldr[i] = W3[(size_t)((c) * 16 + k) * 128 + n];                 \
    }
#define STW3(buf)                                                      \
    _Pragma("unroll") for (int i = 0; i < 4; i++) {                    \
        int idx = tid + i * 512;                                       \
        int k = idx >> 7, n = idx & 127;                               \
        bs[((buf) * 16 + k) * 132 + n] = ldr[i];                       \
    }
        LOADW3(0);
        STW3(0);
        __syncthreads();

        u64 acc[4][4];
#pragma unroll
        for (int p = 0; p < 4; p++)
#pragma unroll
            for (int j = 0; j < 4; j++) acc[p][j] = 0ull;

        for (int c = 0; c < 16; c++) {
            if (c < 15) { LOADW3(c + 1); }
            const float* bsc = bs + (c & 1) * 16 * 132;
            const float* f2c = fA + c * 16 * SS;
#pragma unroll
            for (int k = 0; k < 16; k++) {
                const ulonglong2* ap = (const ulonglong2*)(f2c + k * SS + rg * 8);
                ulonglong2 A0 = ap[0], A1 = ap[1];
                u64 av[4] = {A0.x, A0.y, A1.x, A1.y};
                float4 q = *(const float4*)(bsc + k * 132 + cg * 4);
                float bv[4] = {q.x, q.y, q.z, q.w};
#pragma unroll
                for (int j = 0; j < 4; j++) {
                    u64 bd = dup2(bv[j]);
#pragma unroll
                    for (int p = 0; p < 4; p++) fma2(acc[p][j], av[p], bd);
                }
            }
            if (c < 15) { STW3((c + 1) & 1); }
            __syncthreads();
        }
#undef LOADW3
#undef STW3
        // write f3 k-major into fA cols 0..127 (f2 fully consumed; sync done)
        float4 cb = *(const float4*)(b3 + cg * 4);
        float bias3[4] = {cb.x, cb.y, cb.z, cb.w};
#pragma unroll
        for (int p = 0; p < 4; p++) {
            int m0 = rg * 8 + 2 * p;
#pragma unroll
            for (int j = 0; j < 4; j++) {
                float o0, o1;
                unpack2(acc[p][j], o0, o1);
                o0 = fmaxf(o0 + bias3[j], 0.f);
                o1 = fmaxf(o1 + bias3[j], 0.f);
                *(u64*)&fA[(cg * 4 + j) * SS + m0] = pack2(o0, o1);
            }
        }
    }
    __syncthreads();

    // ================= phase 4: f4 = relu(f3 @ W4 + b4), K=128 ================
    {
        const int tr4 = tid >> 3;        // 64 groups, rows tr4*2
        const int tc4 = tid & 7;         // x4 cols
        u64 acc[4] = {0ull, 0ull, 0ull, 0ull};
#pragma unroll 4
        for (int k = 0; k < 128; k++) {
            u64 a = *(const u64*)&fA[k * SS + tr4 * 2];
            float4 q = *(const float4*)&W4[k * 32 + tc4 * 4];
            float bv[4] = {q.x, q.y, q.z, q.w};
#pragma unroll
            for (int j = 0; j < 4; j++) fma2(acc[j], a, dup2(bv[j]));
        }
        float4 cb = *(const float4*)(b4 + tc4 * 4);
        float bias4[4] = {cb.x, cb.y, cb.z, cb.w};
        __syncthreads();   // f3 reads done before faux overwrite (xsk dead long ago)
#pragma unroll
        for (int j = 0; j < 4; j++) {
            float o0, o1;
            unpack2(acc[j], o0, o1);
            o0 = fmaxf(o0 + bias4[j], 0.f);
            o1 = fmaxf(o1 + bias4[j], 0.f);
            *(u64*)&faux[(tc4 * 4 + j) * SS + tr4 * 2] = pack2(o0, o1);
        }
        if (tid < 128) {
            int n = rowBase + tid;
            faux[32 * SS + tid] = loc[2 * n];
            faux[33 * SS + tid] = loc[2 * n + 1];
            faux[34 * SS + tid] = eng[n];
            faux[35 * SS + tid] = 0.f;
        }
    }
    __syncthreads();

    // ================= phase gx: gates = f4e @ Wg + bg, K=36 ==================
    {
        const int rg = tid >> 6;         // 8 groups x 16 rows
        const int cg = tid & 63;         // x4 cols per 256-col pass
        for (int pc = 0; pc < 2; pc++) {
            u64 acc[8][4];
#pragma unroll
            for (int p = 0; p < 8; p++)
#pragma unroll
                for (int j = 0; j < 4; j++) acc[p][j] = 0ull;

#pragma unroll 4
            for (int k = 0; k < 36; k++) {
                const ulonglong2* ap = (const ulonglong2*)(faux + k * SS + rg * 16);
                ulonglong2 A0 = ap[0], A1 = ap[1], A2 = ap[2], A3 = ap[3];
                u64 av[8] = {A0.x, A0.y, A1.x, A1.y, A2.x, A2.y, A3.x, A3.y};
                float4 q = *(const float4*)&wg[k * 512 + pc * 256 + cg * 4];
                float bv[4] = {q.x, q.y, q.z, q.w};
#pragma unroll
                for (int j = 0; j < 4; j++) {
                    u64 bd = dup2(bv[j]);
#pragma unroll
                    for (int p = 0; p < 8; p++) fma2(acc[p][j], av[p], bd);
                }
            }
            float4 cb = *(const float4*)(bg + pc * 256 + cg * 4);
            float bias0[4] = {cb.x, cb.y, cb.z, cb.w};
#pragma unroll
            for (int p = 0; p < 8; p++) {
                int m0 = rowBase + rg * 16 + 2 * p;
                float o0[4], o1[4];
#pragma unroll
                for (int j = 0; j < 4; j++) {
                    unpack2(acc[p][j], o0[j], o1[j]);
                    o0[j] += bias0[j];
                    o1[j] += bias0[j];
                }
                *(float4*)&gx[(size_t)m0 * 512 + pc * 256 + cg * 4] =
                    make_float4(o0[0], o0[1], o0[2], o0[3]);
                *(float4*)&gx[(size_t)(m0 + 1) * 512 + pc * 256 + cg * 4] =
                    make_float4(o1[0], o1[1], o1[2], o1[3]);
            }
        }
    }
}

// ---------------------------------------------------------------------------
// LSTM v6: 32 rows/CTA (128 CTAs, 1/SM), coalesced WhhT, gx prefetch,
// 2 barriers/step, mask folded, HW-tanh activations, h streamed to global.
// ---------------------------------------------------------------------------
#define LROWS 32
#define HS_STR 36
#define GS_STR 34

__global__ __launch_bounds__(512) void lstm_v6(
    const float* __restrict__ gx, const int* __restrict__ done,
    const float* __restrict__ h0, const float* __restrict__ c0,
    const float* __restrict__ whT, float* __restrict__ hs)
{
    extern __shared__ float sm[];
    float* h_s = sm;                        // [HID][HS_STR]
    float* gs  = h_s + HID * HS_STR;        // [512][GS_STR]
    float* msall = gs + 512 * GS_STR;       // [T_LEN*32]

    const int tid = threadIdx.x;
    const int r0 = blockIdx.x * LROWS;

    float creg[8];
#pragma unroll
    for (int i = 0; i < 8; i++) {
        int e = tid + i * 512;
        int k = e >> 5, r = e & 31;
        h_s[k * HS_STR + r] = h0[(r0 + r) * HID + k];
        creg[i] = c0[(r0 + r) * HID + k];
    }
#pragma unroll
    for (int i = 0; i < 8; i++) {
        int e = tid + i * 512;
        int t = e >> 5, r = e & 31;
        msall[e] = done[t * B_ENV + r0 + r] ? 0.f : 1.f;
    }
    __syncthreads();

    for (int t = 0; t < T_LEN; t++) {
        const float* gp = gx + ((size_t)t * B_ENV + r0) * 512 + tid;
        u64 gxp[16];
#pragma unroll
        for (int p = 0; p < 16; p++)
            gxp[p] = pack2(gp[(size_t)(2 * p) * 512], gp[(size_t)(2 * p + 1) * 512]);

        if (t > 0) {
#pragma unroll
            for (int i = 0; i < 8; i++) {
                int e = tid + i * 512;
                int k = e & 127, r = e >> 7;
                hs[((size_t)(t - 1) * B_ENV + r0 + r) * HID + k] = h_s[k * HS_STR + r];
            }
        }

        {
            u64 macc[16];
#pragma unroll
            for (int p = 0; p < 16; p++) macc[p] = 0ull;

            const float* wp = whT + tid;
#pragma unroll 4
            for (int k = 0; k < HID; k++) {
                u64 wd = dup2(wp[(size_t)k * 512]);
                const ulonglong2* hp = (const ulonglong2*)(h_s + k * HS_STR);
                ulonglong2 H0 = hp[0], H1 = hp[1], H2 = hp[2], H3 = hp[3];
                ulonglong2 H4 = hp[4], H5 = hp[5], H6 = hp[6], H7 = hp[7];
                fma2(macc[0], wd, H0.x);  fma2(macc[1], wd, H0.y);
                fma2(macc[2], wd, H1.x);  fma2(macc[3], wd, H1.y);
                fma2(macc[4], wd, H2.x);  fma2(macc[5], wd, H2.y);
                fma2(macc[6], wd, H3.x);  fma2(macc[7], wd, H3.y);
                fma2(macc[8], wd, H4.x);  fma2(macc[9], wd, H4.y);
                fma2(macc[10], wd, H5.x); fma2(macc[11], wd, H5.y);
                fma2(macc[12], wd, H6.x); fma2(macc[13], wd, H6.y);
                fma2(macc[14], wd, H7.x); fma2(macc[15], wd, H7.y);
            }
            const float* ms = &msall[t * 32];
#pragma unroll
            for (int p = 0; p < 16; p++) {
                u64 mp = pack2(ms[2 * p], ms[2 * p + 1]);
                *(u64*)&gs[tid * GS_STR + 2 * p] = fma2o(macc[p], mp, gxp[p]);
            }
        }
        __syncthreads();

#pragma unroll
        for (int i = 0; i < 8; i++) {
            int e = tid + i * 512;
            int k = e >> 5, r = e & 31;
            float m = msall[t * 32 + r];
            float ig = gs[k * GS_STR + r];
            float fg = gs[(HID + k) * GS_STR + r];
            float gg = gs[(2 * HID + k) * GS_STR + r];
            float og = gs[(3 * HID + k) * GS_STR + r];
            float c = fsig(fg) * (creg[i] * m) + fsig(ig) * ftanh(gg);
            creg[i] = c;
            h_s[k * HS_STR + r] = fsig(og) * ftanh(c);
        }
        __syncthreads();
    }

#pragma unroll
    for (int i = 0; i < 8; i++) {
        int e = tid + i * 512;
        int k = e & 127, r = e >> 7;
        hs[((size_t)(T_LEN - 1) * B_ENV + r0 + r) * HID + k] = h_s[k * HS_STR + r];
    }
}

// ---------------------------------------------------------------------------
// Heads post-pass
// ---------------------------------------------------------------------------
__global__ __launch_bounds__(512) void heads_kernel(
    const float* __restrict__ hs,
    const float* __restrict__ Wa, const float* __restrict__ ba,
    const float* __restrict__ Wc, const float* __restrict__ bc,
    float* __restrict__ out)
{
    __shared__ float w[HID * 8];
    __shared__ float bsh[8];

    const int tid = threadIdx.x;
    for (int i = tid; i < HID * 8; i += 512) {
        int k = i >> 3, c = i & 7;
        float v = 0.f;
        if (c < NA) v = Wa[k * NA + c];
        else if (c == NA) v = Wc[k];
        w[i] = v;
    }
    if (tid < 8) bsh[tid] = (tid < NA) ? ba[tid] : ((tid == NA) ? bc[0] : 0.f);
    __syncthreads();

    const size_t n = (size_t)blockIdx.x * 512 + tid;
    const float* hrow = hs + n * HID;
    float acc[7];
#pragma unroll
    for (int c = 0; c < 7; c++) acc[c] = bsh[c];
#pragma unroll 8
    for (int k = 0; k < HID; k += 4) {
        float4 h4 = *(const float4*)(hrow + k);
        float hv[4] = {h4.x, h4.y, h4.z, h4.w};
#pragma unroll
        for (int s = 0; s < 4; s++)
#pragma unroll
            for (int c = 0; c < 7; c++) acc[c] += hv[s] * w[(k + s) * 8 + c];
    }
    float* dst = out + n * 7;
#pragma unroll
    for (int c = 0; c < 7; c++) dst[c] = acc[c];
}

// ---------------------------------------------------------------------------
// Launch
// ---------------------------------------------------------------------------
extern "C" void kernel_launch(void* const* d_in, const int* in_sizes, int n_in,
                              void* d_out, int out_size)
{
    const float* image = (const float*)d_in[0];
    const float* location = (const float*)d_in[1];
    const float* energy = (const float*)d_in[2];
    const int*   done  = (const int*)d_in[3];
    const float* h0 = (const float*)d_in[4];
    const float* c0 = (const float*)d_in[5];
    const float* W1 = (const float*)d_in[6];
    const float* b1 = (const float*)d_in[7];
    const float* W2 = (const float*)d_in[8];
    const float* b2 = (const float*)d_in[9];
    const float* W3 = (const float*)d_in[10];
    const float* b3 = (const float*)d_in[11];
    const float* W4 = (const float*)d_in[12];
    const float* b4 = (const float*)d_in[13];
    const float* Wl = (const float*)d_in[14];
    const float* bl = (const float*)d_in[15];
    const float* We = (const float*)d_in[16];
    const float* be = (const float*)d_in[17];
    const float* Wih = (const float*)d_in[18];
    const float* Whh = (const float*)d_in[19];
    const float* bih = (const float*)d_in[20];
    const float* bhh = (const float*)d_in[21];
    const float* Wa = (const float*)d_in[22];
    const float* ba = (const float*)d_in[23];
    const float* Wc = (const float*)d_in[24];
    const float* bc = (const float*)d_in[25];
    float* out = (float*)d_out;

    float *phs, *pgx, *pwg, *pbg, *pwhT;
    cudaGetSymbolAddress((void**)&phs, g_hs);
    cudaGetSymbolAddress((void**)&pgx, g_gx);
    cudaGetSymbolAddress((void**)&pwg, g_wg);
    cudaGetSymbolAddress((void**)&pbg, g_bg);
    cudaGetSymbolAddress((void**)&pwhT, g_whT);

    prep_wg<<<(36 * 512 + 255) / 256, 256>>>(Wih, Wl, We, pwg);
    prep_bg<<<2, 256>>>(Wih, bl, be, bih, bhh, pbg);
    prep_whT<<<(HID * 512 + 255) / 256, 256>>>(Whh, pwhT);

    const int smemM = (256 * SS + 36 * SS + 32 * 264) * 4;              // 187,968 B
    const int smemL = (HID * HS_STR + 512 * GS_STR + T_LEN * 32) * 4;   // 104,448 B
    cudaFuncSetAttribute(mega_enc, cudaFuncAttributeMaxDynamicSharedMemorySize, smemM);
    cudaFuncSetAttribute(lstm_v6, cudaFuncAttributeMaxDynamicSharedMemorySize, smemL);

    mega_enc<<<N_TOT / 128, 512, smemM>>>(image, location, energy,
                                          W1, b1, W2, b2, W3, b3, W4, b4,
                                          pwg, pbg, pgx);
    lstm_v6<<<B_ENV / LROWS, 512, smemL>>>(pgx, done, h0, c0, pwhT, phs);
    heads_kernel<<<N_TOT / 512, 512>>>(phs, Wa, ba, Wc, bc, out);
}